// round 13
// baseline (speedup 1.0000x reference)
#include <cuda_runtime.h>
#include <math.h>

#define BATCH 16
#define PIX   22500          // 150*150
#define HB    61
#define SPLITK 12
#define KT    32
#define KCH   1888           // 12*1888 = 22656 >= 22500, multiple of KT

#define KSTR  68             // padded row stride (floats)
#define BUF_FLOATS (2 * KT * KSTR)               // U+V planes = 4352 floats
#define HIST_SMEM (2 * BUF_FLOATS * 4)           // 34816 B

#define E_HIST (3*HB*HB)     // 11163
#define C1_PER (128*29*29)   // 107648
#define C2_PER (256*14*14)   // 50176
#define C3_PER (512*13*13)   // 86528

typedef unsigned long long ull;

__device__ __forceinline__ ull pack2(float x, float y) {
    ull r; asm("mov.b64 %0, {%1, %2};" : "=l"(r) : "f"(x), "f"(y)); return r;
}
__device__ __forceinline__ void unpack2(ull v, float& x, float& y) {
    asm("mov.b64 {%0, %1}, %2;" : "=f"(x), "=f"(y) : "l"(v));
}
__device__ __forceinline__ void ffma2(ull& d, ull a, ull b) {
    asm("fma.rn.f32x2 %0, %1, %2, %3;" : "=l"(d) : "l"(a), "l"(b), "l"(d));
}

// -------- scratch --------
__device__ float g_luv[BATCH*4*PIX];
__device__ float g_hist_part[SPLITK][BATCH*E_HIST];
__device__ float g_bsum[BATCH*8];
__device__ float g_c1[BATCH*C1_PER];
__device__ float g_c2p[4][BATCH*C2_PER];
__device__ float g_c3p[4][BATCH*C3_PER];
__device__ float g_c3[BATCH*C3_PER];
__device__ float g_fc[BATCH*9];
__device__ float g_m[BATCH*9];
__device__ float g_minv[BATCH*9];

// tiny kernels to keep hist_kernel in the ncu capture slot (4th launch)
__global__ void zero_bsum_kernel() {
    int i = threadIdx.x;
    if (i < BATCH * 8) g_bsum[i] = 0.f;
}
__global__ void zero_fc_kernel() {
    int i = threadIdx.x;
    if (i < BATCH * 9) g_fc[i] = 0.f;
}

// ============================================================
// prep: image -> (lr,lg,lb,iy). mode 1: apply g_m first
// ============================================================
__global__ void prep_kernel(const float* __restrict__ img, int mapped)
{
    int idx = blockIdx.x * 256 + threadIdx.x;
    if (idx >= BATCH * PIX) return;
    int b = idx / PIX;
    int p = idx - b * PIX;
    float r  = img[(size_t)(b * 3 + 0) * PIX + p];
    float g  = img[(size_t)(b * 3 + 1) * PIX + p];
    float bl = img[(size_t)(b * 3 + 2) * PIX + p];
    if (mapped) {
        const float* M = &g_m[b * 9];
        float r2  = M[0]*r + M[1]*g + M[2]*bl;
        float g2  = M[3]*r + M[4]*g + M[5]*bl;
        float bl2 = M[6]*r + M[7]*g + M[8]*bl;
        r = r2; g = g2; bl = bl2;
    }
    r  = fminf(fmaxf(r, 0.f), 1.f);
    g  = fminf(fmaxf(g, 0.f), 1.f);
    bl = fminf(fmaxf(bl, 0.f), 1.f);
    float iy = sqrtf(r*r + g*g + bl*bl);
    g_luv[(size_t)(b*4 + 0)*PIX + p] = logf(r + 1e-6f);
    g_luv[(size_t)(b*4 + 1)*PIX + p] = logf(g + 1e-6f);
    g_luv[(size_t)(b*4 + 2)*PIX + p] = logf(bl + 1e-6f);
    g_luv[(size_t)(b*4 + 3)*PIX + p] = iy;
}

// ============================================================
// Histogram: warp-specialized producer/consumer, double-buffered.
// KT=32 tiles so 4 blocks/SM fit (34.8KB smem). Builders: 2 threads per
// row (halves split zero + up/down chains, __syncwarp between).
// ============================================================
__global__ void __launch_bounds__(256, 4)
hist_kernel(const float* __restrict__ su,
            const float* __restrict__ sv,
            const float* __restrict__ cpar)
{
    extern __shared__ __align__(16) float smemDyn[];   // [2][BUF_FLOATS]

    int blk = blockIdx.x;
    int ks  = blk % SPLITK;
    int bc  = blk / SPLITK;
    int c   = bc % 3;
    int b   = bc / 3;

    float sg_u = su[c], sg_v = sv[c];
    float inv_u2 = 1.0f / (sg_u * sg_u);
    float inv_v2 = 1.0f / (sg_v * sg_v);
    float cw = cpar[c];

    int tid = threadIdx.x;          // 256
    bool is_builder = (tid < 128);

    // builder identity: 2 threads per row
    int row  = tid >> 1;            // 0..63
    int half = tid & 1;             // 0: zero lo half + center/up; 1: zero hi half + down
    int pl   = row & 31;            // pixel lane within tile
    int isV  = row >> 5;            // 0: U plane, 1: V plane
    float inv2 = isV ? inv_v2 : inv_u2;
    float q    = __expf(-0.02f * inv2);

    // consumer identity
    int lx = tid - 128;             // 0..127
    int tx = lx & 15;               // v: bins tx*4 .. tx*4+3
    int ty = lx >> 4;               // u: bins ty*8 .. ty*8+7

    ull acc[8][2];
#pragma unroll
    for (int a = 0; a < 8; a++) { acc[a][0] = 0ULL; acc[a][1] = 0ULL; }

    int k0 = ks * KCH;
    int k1 = min(k0 + KCH, PIX);
    int T  = (k1 - k0 + KT - 1) / KT;
    const float* luv = g_luv + (size_t)b * 4 * PIX;

    for (int t = 0; t < T + 1; t++) {
        if (is_builder && t < T) {
            float* base = smemDyn + (t & 1) * BUF_FLOATS;
            float* rowp = base + isV * (KT * KSTR) + pl * KSTR;
            // zero own half of the row (bins 0-31 or 32-63)
            float4 z4 = make_float4(0.f, 0.f, 0.f, 0.f);
#pragma unroll
            for (int i = 0; i < 8; i++) ((float4*)rowp)[half * 8 + i] = z4;

            int p = k0 + t * KT + pl;
            bool valid = (p < k1);
            int pp = valid ? p : 0;
            float la  = luv[pp];
            float lgg = luv[PIX + pp];
            float lbb = luv[2*PIX + pp];
            float x, wgt;
            if (!isV) {
                float iy = luv[3*PIX + pp];
                if (c == 0)      x = la - lgg;
                else if (c == 1) x = lgg - la;
                else             x = lbb - la;
                wgt = valid ? iy * cw : 0.f;   // invalid pixel: all-zero U row
            } else {
                if (c == 0)      x = la - lbb;
                else if (c == 1) x = lgg - lbb;
                else             x = lbb - lgg;
                wgt = 1.0f;
            }
            int cb = __float2int_rn((x + 3.0f) * 10.0f);
            cb = max(0, min(60, cb));
            float d = x - (-3.0f + 0.1f * (float)cb);
            float fc0 = __expf(-d * d * inv2) * wgt;
            __syncwarp();   // both halves' zeros visible before window scatter
            if (half == 0) {
                float rup = __expf((0.2f * d - 0.01f) * inv2);
                rowp[cb] = fc0;
                float f = fc0, rr = rup;
#pragma unroll
                for (int j = 1; j <= 16; j++) {
                    f *= rr; rr *= q;
                    int b2 = cb + j;
                    if (b2 <= 60) rowp[b2] = f;
                }
            } else {
                float sdn = __expf((-0.2f * d - 0.01f) * inv2);
                float f = fc0, rr = sdn;
#pragma unroll
                for (int j = 1; j <= 16; j++) {
                    f *= rr; rr *= q;
                    int b2 = cb - j;
                    if (b2 >= 0) rowp[b2] = f;
                }
            }
        }
        if (!is_builder && t > 0) {
            const float* base = smemDyn + ((t - 1) & 1) * BUF_FLOATS;
            const float* bufU = base;
            const float* bufV = base + KT * KSTR;
#pragma unroll 4
            for (int k = 0; k < KT; k++) {
                const float* Urow = bufU + k * KSTR + ty * 8;
                ulonglong2 V = *(const ulonglong2*)(bufV + k * KSTR + tx * 4);
                float4 Ua = *(const float4*)Urow;
                ull u0 = pack2(Ua.x, Ua.x), u1 = pack2(Ua.y, Ua.y);
                ull u2 = pack2(Ua.z, Ua.z), u3 = pack2(Ua.w, Ua.w);
                ffma2(acc[0][0], u0, V.x); ffma2(acc[0][1], u0, V.y);
                ffma2(acc[1][0], u1, V.x); ffma2(acc[1][1], u1, V.y);
                ffma2(acc[2][0], u2, V.x); ffma2(acc[2][1], u2, V.y);
                ffma2(acc[3][0], u3, V.x); ffma2(acc[3][1], u3, V.y);
                float4 Ub = *(const float4*)(Urow + 4);
                u0 = pack2(Ub.x, Ub.x); u1 = pack2(Ub.y, Ub.y);
                u2 = pack2(Ub.z, Ub.z); u3 = pack2(Ub.w, Ub.w);
                ffma2(acc[4][0], u0, V.x); ffma2(acc[4][1], u0, V.y);
                ffma2(acc[5][0], u1, V.x); ffma2(acc[5][1], u1, V.y);
                ffma2(acc[6][0], u2, V.x); ffma2(acc[6][1], u2, V.y);
                ffma2(acc[7][0], u3, V.x); ffma2(acc[7][1], u3, V.y);
            }
        }
        __syncthreads();
    }

    // consumers write their 8x4 region
    if (!is_builder) {
        float* out = &g_hist_part[ks][(size_t)b * E_HIST + c * HB * HB];
#pragma unroll
        for (int a = 0; a < 8; a++) {
            int iu = ty * 8 + a;
            if (iu >= HB) continue;
#pragma unroll
            for (int j = 0; j < 2; j++) {
                float lo, hi;
                unpack2(acc[a][j], lo, hi);
                int iv = tx * 4 + 2 * j;
                if (iv < HB)     out[iu * HB + iv]     = lo;
                if (iv + 1 < HB) out[iu * HB + iv + 1] = hi;
            }
        }
    }
}

// ============================================================
// conv1: [B,3,61,61] -> [B,128,29,29], 5x5 s2, relu.
// SPLITK partial-sum + normalization total folded into the load phase.
// ============================================================
__global__ void conv1_kernel(const float* __restrict__ w, const float* __restrict__ bias)
{
    int octile = blockIdx.x;   // 0..7
    int b      = blockIdx.y;
    __shared__ __align__(16) float sInE[3][61][32];
    __shared__ __align__(16) float sInO[3][61][32];
    __shared__ __align__(16) float sW[1200];   // [ic][tap25][ocl16]
    __shared__ float sRed[512];
    int tx = threadIdx.x;      // 0..28
    int ty = threadIdx.y;      // 0..14
    int tid = ty * 29 + tx;    // 0..434

    float lsum = 0.f;
    for (int i = tid; i < E_HIST; i += 435) {
        float h = 0.f;
#pragma unroll
        for (int s = 0; s < SPLITK; s++) h += g_hist_part[s][b * E_HIST + i];
        int ic = i / 3721; int pos = i - ic * 3721;
        int y = pos / 61;  int x = pos - y * 61;
        if (x & 1) sInO[ic][y][x >> 1] = h;
        else       sInE[ic][y][x >> 1] = h;
        lsum += h;
    }
    for (int i = tid; i < 1200; i += 435) {
        int ocl = i & 15; int rest = i >> 4;
        sW[i] = w[(size_t)(octile * 16 + ocl) * 75 + rest];
    }
    sRed[tid] = lsum;
    if (tid < 77) sRed[435 + tid] = 0.f;
    __syncthreads();
    for (int s = 256; s > 0; s >>= 1) {
        if (tid < s) sRed[tid] += sRed[tid + s];
        __syncthreads();
    }
    float inv = 1.0f / (sRed[0] + 1e-6f);

    ull acc[2][8];
#pragma unroll
    for (int p = 0; p < 2; p++)
#pragma unroll
        for (int t = 0; t < 8; t++) acc[p][t] = 0ULL;

    int r1 = min(ty + 15, 28);

#pragma unroll 1
    for (int ic = 0; ic < 3; ic++) {
#pragma unroll
        for (int ky = 0; ky < 5; ky++)
#pragma unroll
            for (int kx = 0; kx < 5; kx++) {
                int xi = tx + (kx >> 1);
                const float (*P)[32] = (kx & 1) ? sInO[ic] : sInE[ic];
                float v0 = P[2 * ty + ky][xi];
                float v1 = P[2 * r1 + ky][xi];
                ull p0 = pack2(v0, v0);
                ull p1 = pack2(v1, v1);
                const ulonglong2* wk = (const ulonglong2*)&sW[(ic * 25 + ky * 5 + kx) * 16];
                ulonglong2 wa = wk[0], wb = wk[1];
                ffma2(acc[0][0], p0, wa.x); ffma2(acc[0][1], p0, wa.y);
                ffma2(acc[0][2], p0, wb.x); ffma2(acc[0][3], p0, wb.y);
                ffma2(acc[1][0], p1, wa.x); ffma2(acc[1][1], p1, wa.y);
                ffma2(acc[1][2], p1, wb.x); ffma2(acc[1][3], p1, wb.y);
                ulonglong2 wc = wk[2], wd = wk[3];
                ffma2(acc[0][4], p0, wc.x); ffma2(acc[0][5], p0, wc.y);
                ffma2(acc[0][6], p0, wd.x); ffma2(acc[0][7], p0, wd.y);
                ffma2(acc[1][4], p1, wc.x); ffma2(acc[1][5], p1, wc.y);
                ffma2(acc[1][6], p1, wd.x); ffma2(acc[1][7], p1, wd.y);
            }
    }

#pragma unroll
    for (int p = 0; p < 2; p++) {
        int oy = ty + p * 15;
        if (oy > 28) continue;
#pragma unroll
        for (int t = 0; t < 8; t++) {
            float lo, hi;
            unpack2(acc[p][t], lo, hi);
            int oc = octile * 16 + 2 * t;
            g_c1[((size_t)(b * 128 + oc) * 29 + oy) * 29 + tx]     = fmaxf(bias[oc]     + inv * lo, 0.f);
            g_c1[((size_t)(b * 128 + oc + 1) * 29 + oy) * 29 + tx] = fmaxf(bias[oc + 1] + inv * hi, 0.f);
        }
    }
}

// ============================================================
// conv2: [B,128,29,29] -> partials [4][B,256,14,14], 3x3 s2
// ============================================================
__global__ void conv2_kernel(const float* __restrict__ w)
{
    int octile = blockIdx.x;   // 0..7 (32 oc)
    int b      = blockIdx.y;
    int ks     = blockIdx.z;   // 0..3 (ic chunk of 32)
    __shared__ __align__(16) float sInE[8][29][16];
    __shared__ __align__(16) float sInO[8][29][16];
    __shared__ __align__(16) float sW[8 * 9 * 32];
    int tx = threadIdx.x;      // 0..13
    int ty = threadIdx.y;      // 0..6
    int z  = threadIdx.z;      // 0..1
    int tid = (z * 7 + ty) * 14 + tx;  // 0..195

    ull acc[2][8];
#pragma unroll
    for (int p = 0; p < 2; p++)
#pragma unroll
        for (int t = 0; t < 8; t++) acc[p][t] = 0ULL;

    for (int s = 0; s < 4; s++) {
        int icg = ks * 32 + s * 8;
        __syncthreads();
        for (int i = tid; i < 8 * 841; i += 196) {
            int ic = i / 841; int pos = i - ic * 841;
            int y = pos / 29; int x = pos - y * 29;
            float v = g_c1[(size_t)(b * 128 + icg) * 841 + i];
            if (x & 1) sInO[ic][y][x >> 1] = v;
            else       sInE[ic][y][x >> 1] = v;
        }
        for (int i = tid; i < 2304; i += 196) {
            int ocl = i & 31;
            int k   = (i >> 5) % 9;
            int ic  = i / 288;
            sW[i] = w[((size_t)(octile * 32 + ocl) * 128 + icg + ic) * 9 + k];
        }
        __syncthreads();
#pragma unroll
        for (int ic = 0; ic < 8; ic++) {
            const float* wp = &sW[ic * 288 + z * 16];
#pragma unroll
            for (int ky = 0; ky < 3; ky++)
#pragma unroll
                for (int kx = 0; kx < 3; kx++) {
                    int xi = tx + (kx >> 1);
                    const float (*P)[16] = (kx & 1) ? sInO[ic] : sInE[ic];
                    float v0 = P[2 * ty + ky][xi];
                    float v1 = P[2 * ty + ky + 14][xi];
                    ull p0 = pack2(v0, v0);
                    ull p1 = pack2(v1, v1);
                    const ulonglong2* wk = (const ulonglong2*)(wp + (ky * 3 + kx) * 32);
                    ulonglong2 wa = wk[0], wb = wk[1];
                    ffma2(acc[0][0], p0, wa.x); ffma2(acc[0][1], p0, wa.y);
                    ffma2(acc[0][2], p0, wb.x); ffma2(acc[0][3], p0, wb.y);
                    ffma2(acc[1][0], p1, wa.x); ffma2(acc[1][1], p1, wa.y);
                    ffma2(acc[1][2], p1, wb.x); ffma2(acc[1][3], p1, wb.y);
                    ulonglong2 wc = wk[2], wd = wk[3];
                    ffma2(acc[0][4], p0, wc.x); ffma2(acc[0][5], p0, wc.y);
                    ffma2(acc[0][6], p0, wd.x); ffma2(acc[0][7], p0, wd.y);
                    ffma2(acc[1][4], p1, wc.x); ffma2(acc[1][5], p1, wc.y);
                    ffma2(acc[1][6], p1, wd.x); ffma2(acc[1][7], p1, wd.y);
                }
        }
    }
    float* outp = &g_c2p[ks][(size_t)b * C2_PER];
#pragma unroll
    for (int p = 0; p < 2; p++) {
        int oy = ty + p * 7;
#pragma unroll
        for (int t = 0; t < 8; t++) {
            float lo, hi;
            unpack2(acc[p][t], lo, hi);
            int oc = octile * 32 + z * 16 + 2 * t;
            outp[((size_t)oc * 14 + oy) * 14 + tx]       = lo;
            outp[((size_t)(oc + 1) * 14 + oy) * 14 + tx] = hi;
        }
    }
}

// ============================================================
// conv3: conv2 partial-reduce + bias + relu fused into smem fill.
// [B,256,14,14] -> partials [4][B,512,13,13], 2x2 s1
// ============================================================
__global__ void conv3_kernel(const float* __restrict__ w, const float* __restrict__ bias2)
{
    int octile = blockIdx.x;   // 0..15
    int b      = blockIdx.y;
    int ks     = blockIdx.z;   // 0..3 (ic chunk of 64)
    __shared__ __align__(16) float sIn[16 * 210];
    __shared__ __align__(16) float sW[16 * 4 * 32];
    int tx = threadIdx.x;      // 0..12
    int ty = threadIdx.y;      // 0..6
    int z  = threadIdx.z;      // 0..1
    int tid = (z * 7 + ty) * 13 + tx;  // 0..181

    for (int i = tid; i < 16 * 210; i += 182) sIn[i] = 0.f;

    ull acc[2][8];
#pragma unroll
    for (int p = 0; p < 2; p++)
#pragma unroll
        for (int t = 0; t < 8; t++) acc[p][t] = 0ULL;

    for (int s = 0; s < 4; s++) {
        int icg = ks * 64 + s * 16;
        __syncthreads();
        for (int i = tid; i < 16 * 196; i += 182) {
            int icl = i / 196, pos = i - icl * 196;
            size_t gidx = (size_t)(b * 256 + icg + icl) * 196 + pos;
            float v = bias2[icg + icl];
#pragma unroll
            for (int k = 0; k < 4; k++) v += g_c2p[k][gidx];
            sIn[icl * 210 + pos] = fmaxf(v, 0.f);
        }
        for (int i = tid; i < 2048; i += 182) {
            int ocl = i & 31;
            int k   = (i >> 5) & 3;
            int ic  = i >> 7;
            sW[i] = w[((size_t)(octile * 32 + ocl) * 256 + icg + ic) * 4 + k];
        }
        __syncthreads();
#pragma unroll
        for (int ic = 0; ic < 16; ic++) {
            const float* ip = &sIn[ic * 210 + ty * 14 + tx];
            const float* wp = &sW[ic * 128 + z * 16];
#pragma unroll
            for (int ky = 0; ky < 2; ky++)
#pragma unroll
                for (int kx = 0; kx < 2; kx++) {
                    float v0 = ip[ky * 14 + kx];
                    float v1 = ip[ky * 14 + kx + 98];
                    ull p0 = pack2(v0, v0);
                    ull p1 = pack2(v1, v1);
                    const ulonglong2* wk = (const ulonglong2*)(wp + (ky * 2 + kx) * 32);
                    ulonglong2 wa = wk[0], wb = wk[1];
                    ffma2(acc[0][0], p0, wa.x); ffma2(acc[0][1], p0, wa.y);
                    ffma2(acc[0][2], p0, wb.x); ffma2(acc[0][3], p0, wb.y);
                    ffma2(acc[1][0], p1, wa.x); ffma2(acc[1][1], p1, wa.y);
                    ffma2(acc[1][2], p1, wb.x); ffma2(acc[1][3], p1, wb.y);
                    ulonglong2 wc = wk[2], wd = wk[3];
                    ffma2(acc[0][4], p0, wc.x); ffma2(acc[0][5], p0, wc.y);
                    ffma2(acc[0][6], p0, wd.x); ffma2(acc[0][7], p0, wd.y);
                    ffma2(acc[1][4], p1, wc.x); ffma2(acc[1][5], p1, wc.y);
                    ffma2(acc[1][6], p1, wd.x); ffma2(acc[1][7], p1, wd.y);
                }
        }
    }
    float* outp = &g_c3p[ks][(size_t)b * C3_PER];
#pragma unroll
    for (int p = 0; p < 2; p++) {
        int oy = ty + p * 7;
        if (oy > 12) continue;
#pragma unroll
        for (int t = 0; t < 8; t++) {
            float lo, hi;
            unpack2(acc[p][t], lo, hi);
            int oc = octile * 32 + z * 16 + 2 * t;
            outp[((size_t)oc * 13 + oy) * 13 + tx]       = lo;
            outp[((size_t)(oc + 1) * 13 + oy) * 13 + tx] = hi;
        }
    }
}

__global__ void conv3_reduce_kernel(const float* __restrict__ bias)
{
    int idx = blockIdx.x * 256 + threadIdx.x;
    if (idx >= BATCH * C3_PER) return;
    int within = idx % C3_PER;
    int oc = within / 169;
    float s = bias[oc];
#pragma unroll
    for (int k = 0; k < 4; k++) s += g_c3p[k][idx];
    g_c3[idx] = fmaxf(s, 0.f);
}

// ============================================================
// fc: [B, 86528] @ W[OUT, 86528]^T -> abs
// ============================================================
__global__ void fc_kernel(const float* __restrict__ w, int OUT)
{
    int o = blockIdx.x % OUT;
    int b = blockIdx.x / OUT;
    int tid = threadIdx.x;   // 256
    const float4* a  = (const float4*)&g_c3[(size_t)b * C3_PER];
    const float4* wv = (const float4*)(w + (size_t)o * C3_PER);
    float s = 0.f;
    for (int i = tid; i < C3_PER / 4; i += 256) {
        float4 x = a[i], y = wv[i];
        s += x.x*y.x + x.y*y.y + x.z*y.z + x.w*y.w;
    }
    __shared__ float red[256];
    red[tid] = s;
    __syncthreads();
    for (int st = 128; st > 0; st >>= 1) {
        if (tid < st) red[tid] += red[tid + st];
        __syncthreads();
    }
    if (tid == 0) g_fc[b * OUT + o] = fabsf(red[0]);
}

// ============================================================
__global__ void matrix_kernel()
{
    int b = threadIdx.x;
    if (b >= BATCH) return;
    float v[9];
#pragma unroll
    for (int k = 0; k < 9; k++) v[k] = g_fc[b * 9 + k];
    float m[3][3];
#pragma unroll
    for (int i = 0; i < 3; i++)
#pragma unroll
        for (int j = 0; j < 3; j++) m[i][j] = v[j * 3 + i];
    float n = 0.f;
#pragma unroll
    for (int i = 0; i < 3; i++) {
        float rs = fabsf(m[i][0]) + fabsf(m[i][1]) + fabsf(m[i][2]);
        n = fmaxf(n, rs);
    }
    n += 1e-4f;
    float inv_n = 1.0f / n;
#pragma unroll
    for (int i = 0; i < 3; i++)
#pragma unroll
        for (int j = 0; j < 3; j++) {
            m[i][j] *= inv_n;
            g_m[b * 9 + i * 3 + j] = m[i][j];
        }
    float c00 = m[1][1]*m[2][2] - m[1][2]*m[2][1];
    float c01 = m[1][0]*m[2][2] - m[1][2]*m[2][0];
    float c02 = m[1][0]*m[2][1] - m[1][1]*m[2][0];
    float det = m[0][0]*c00 - m[0][1]*c01 + m[0][2]*c02;
    float id = 1.0f / det;
    g_minv[b*9 + 0] =  c00 * id;
    g_minv[b*9 + 1] = (m[0][2]*m[2][1] - m[0][1]*m[2][2]) * id;
    g_minv[b*9 + 2] = (m[0][1]*m[1][2] - m[0][2]*m[1][1]) * id;
    g_minv[b*9 + 3] = -c01 * id;
    g_minv[b*9 + 4] = (m[0][0]*m[2][2] - m[0][2]*m[2][0]) * id;
    g_minv[b*9 + 5] = (m[0][2]*m[1][0] - m[0][0]*m[1][2]) * id;
    g_minv[b*9 + 6] =  c02 * id;
    g_minv[b*9 + 7] = (m[0][1]*m[2][0] - m[0][0]*m[2][1]) * id;
    g_minv[b*9 + 8] = (m[0][0]*m[1][1] - m[0][1]*m[1][0]) * id;
}

__global__ void final_kernel(float* __restrict__ out)
{
    int b = threadIdx.x;
    if (b >= BATCH) return;
    float il[3];
#pragma unroll
    for (int j = 0; j < 3; j++) il[j] = g_fc[b * 3 + j];
#pragma unroll
    for (int i = 0; i < 3; i++)
        out[b * 3 + i] = g_minv[b*9 + i*3 + 0] * il[0]
                       + g_minv[b*9 + i*3 + 1] * il[1]
                       + g_minv[b*9 + i*3 + 2] * il[2];
}

// ============================================================
extern "C" void kernel_launch(void* const* d_in, const int* in_sizes, int n_in,
                              void* d_out, int out_size)
{
    const float* image = (const float*)d_in[0];
    const float* su_s  = (const float*)d_in[1];
    const float* sv_s  = (const float*)d_in[2];
    const float* c_s   = (const float*)d_in[3];
    const float* w1_s  = (const float*)d_in[4];
    const float* b1_s  = (const float*)d_in[5];
    const float* w2_s  = (const float*)d_in[6];
    const float* b2_s  = (const float*)d_in[7];
    const float* w3_s  = (const float*)d_in[8];
    const float* b3_s  = (const float*)d_in[9];
    const float* fc_s  = (const float*)d_in[10];
    const float* su_i  = (const float*)d_in[11];
    const float* sv_i  = (const float*)d_in[12];
    const float* c_i   = (const float*)d_in[13];
    const float* w1_i  = (const float*)d_in[14];
    const float* b1_i  = (const float*)d_in[15];
    const float* w2_i  = (const float*)d_in[16];
    const float* b2_i  = (const float*)d_in[17];
    const float* w3_i  = (const float*)d_in[18];
    const float* b3_i  = (const float*)d_in[19];
    const float* fc_i  = (const float*)d_in[20];

    static int smem_set = 0;
    if (!smem_set) {
        cudaFuncSetAttribute(hist_kernel,
                             cudaFuncAttributeMaxDynamicSharedMemorySize, HIST_SMEM);
        smem_set = 1;
    }

    dim3 cb1(29, 15), cb2(14, 7, 2), cb3(13, 7, 2);
    dim3 cg1(8, BATCH), cg2(8, BATCH, 4), cg3(16, BATCH, 4);
    int prep_blocks = (BATCH * PIX + 255) / 256;
    int c3r_blocks = (BATCH * C3_PER + 255) / 256;

    // ---- sensor branch ----
    prep_kernel<<<prep_blocks, 256>>>(image, 0);
    zero_bsum_kernel<<<1, 128>>>();          // capture-slot alignment
    zero_fc_kernel<<<1, 160>>>();            // capture-slot alignment
    hist_kernel<<<BATCH * 3 * SPLITK, 256, HIST_SMEM>>>(su_s, sv_s, c_s);  // 4th -> ncu
    conv1_kernel<<<cg1, cb1>>>(w1_s, b1_s);
    conv2_kernel<<<cg2, cb2>>>(w2_s);
    conv3_kernel<<<cg3, cb3>>>(w3_s, b2_s);
    conv3_reduce_kernel<<<c3r_blocks, 256>>>(b3_s);
    fc_kernel<<<BATCH * 9, 256>>>(fc_s, 9);
    matrix_kernel<<<1, 32>>>();

    // ---- illuminant branch ----
    prep_kernel<<<prep_blocks, 256>>>(image, 1);
    hist_kernel<<<BATCH * 3 * SPLITK, 256, HIST_SMEM>>>(su_i, sv_i, c_i);
    conv1_kernel<<<cg1, cb1>>>(w1_i, b1_i);
    conv2_kernel<<<cg2, cb2>>>(w2_i);
    conv3_kernel<<<cg3, cb3>>>(w3_i, b2_i);
    conv3_reduce_kernel<<<c3r_blocks, 256>>>(b3_i);
    fc_kernel<<<BATCH * 3, 256>>>(fc_i, 3);
    final_kernel<<<1, 32>>>((float*)d_out);
}

// round 14
// speedup vs baseline: 1.1408x; 1.1408x over previous
#include <cuda_runtime.h>
#include <math.h>

#define BATCH 16
#define PIX   22500          // 150*150
#define HB    61
#define SPLITK 9
#define KT    64
#define KCH   2560           // 9*2560 = 23040 >= 22500, multiple of KT

#define KSTR  68             // padded row stride (floats)
#define HIST_SMEM (4 * KT * KSTR * 4)   // 2 buffers x (U+V planes) = 69632 B

#define E_HIST (3*HB*HB)     // 11163
#define C1_PER (128*29*29)   // 107648
#define C2_PER (256*14*14)   // 50176
#define C3_PER (512*13*13)   // 86528

typedef unsigned long long ull;

__device__ __forceinline__ ull pack2(float x, float y) {
    ull r; asm("mov.b64 %0, {%1, %2};" : "=l"(r) : "f"(x), "f"(y)); return r;
}
__device__ __forceinline__ void unpack2(ull v, float& x, float& y) {
    asm("mov.b64 {%0, %1}, %2;" : "=f"(x), "=f"(y) : "l"(v));
}
__device__ __forceinline__ void ffma2(ull& d, ull a, ull b) {
    asm("fma.rn.f32x2 %0, %1, %2, %3;" : "=l"(d) : "l"(a), "l"(b), "l"(d));
}
__device__ __forceinline__ void bar_sync_n(int id) {
    asm volatile("bar.sync %0, 256;" :: "r"(id) : "memory");
}
__device__ __forceinline__ void bar_arrive_n(int id) {
    asm volatile("bar.arrive %0, 256;" :: "r"(id) : "memory");
}

// -------- scratch --------
__device__ float g_luv[BATCH*4*PIX];
__device__ float g_hist_part[SPLITK][BATCH*E_HIST];
__device__ float g_bsum[BATCH*8];
__device__ float g_c1[BATCH*C1_PER];
__device__ float g_c2p[4][BATCH*C2_PER];
__device__ float g_c2[BATCH*C2_PER];
__device__ float g_c3p[4][BATCH*C3_PER];
__device__ float g_c3[BATCH*C3_PER];
__device__ float g_fc[BATCH*9];
__device__ float g_m[BATCH*9];
__device__ float g_minv[BATCH*9];

// tiny kernels to keep hist_kernel in the ncu capture slot (4th launch)
__global__ void zero_bsum_kernel() {
    int i = threadIdx.x;
    if (i < BATCH * 8) g_bsum[i] = 0.f;
}
__global__ void zero_fc_kernel() {
    int i = threadIdx.x;
    if (i < BATCH * 9) g_fc[i] = 0.f;
}

// ============================================================
// prep: image -> (lr,lg,lb,iy). mode 1: apply g_m first
// ============================================================
__global__ void prep_kernel(const float* __restrict__ img, int mapped)
{
    int idx = blockIdx.x * 256 + threadIdx.x;
    if (idx >= BATCH * PIX) return;
    int b = idx / PIX;
    int p = idx - b * PIX;
    float r  = img[(size_t)(b * 3 + 0) * PIX + p];
    float g  = img[(size_t)(b * 3 + 1) * PIX + p];
    float bl = img[(size_t)(b * 3 + 2) * PIX + p];
    if (mapped) {
        const float* M = &g_m[b * 9];
        float r2  = M[0]*r + M[1]*g + M[2]*bl;
        float g2  = M[3]*r + M[4]*g + M[5]*bl;
        float bl2 = M[6]*r + M[7]*g + M[8]*bl;
        r = r2; g = g2; bl = bl2;
    }
    r  = fminf(fmaxf(r, 0.f), 1.f);
    g  = fminf(fmaxf(g, 0.f), 1.f);
    bl = fminf(fmaxf(bl, 0.f), 1.f);
    float iy = sqrtf(r*r + g*g + bl*bl);
    g_luv[(size_t)(b*4 + 0)*PIX + p] = logf(r + 1e-6f);
    g_luv[(size_t)(b*4 + 1)*PIX + p] = logf(g + 1e-6f);
    g_luv[(size_t)(b*4 + 2)*PIX + p] = logf(bl + 1e-6f);
    g_luv[(size_t)(b*4 + 3)*PIX + p] = iy;
}

// ============================================================
// Histogram: warp-specialized producer/consumer with double buffering.
// Split named barriers: builders arrive on full[t&1] and only block on
// empty[t&1] when 2 tiles ahead; consumers sync on full, arrive on empty.
// No full-block rendezvous.
//   full parity0 = bar 1, full parity1 = bar 2
//   empty parity0 = bar 3, empty parity1 = bar 4
// ============================================================
__global__ void __launch_bounds__(256, 3)
hist_kernel(const float* __restrict__ su,
            const float* __restrict__ sv,
            const float* __restrict__ cpar)
{
    extern __shared__ __align__(16) float smemDyn[];   // [2][2][KT*KSTR]

    int blk = blockIdx.x;
    int ks  = blk % SPLITK;
    int bc  = blk / SPLITK;
    int c   = bc % 3;
    int b   = bc / 3;

    float sg_u = su[c], sg_v = sv[c];
    float inv_u2 = 1.0f / (sg_u * sg_u);
    float inv_v2 = 1.0f / (sg_v * sg_v);
    float cw = cpar[c];

    int tid = threadIdx.x;          // 256
    bool is_builder = (tid < 128);

    int k0 = ks * KCH;
    int k1 = min(k0 + KCH, PIX);
    int T  = (k1 - k0 + KT - 1) / KT;
    const float* luv = g_luv + (size_t)b * 4 * PIX;

    if (is_builder) {
        int pl  = tid & 63;             // row (pixel lane)
        int isV = (tid >> 6) & 1;       // 0: U plane, 1: V plane
        float inv2 = isV ? inv_v2 : inv_u2;
        float q    = __expf(-0.02f * inv2);

        for (int t = 0; t < T; t++) {
            if (t >= 2) bar_sync_n(3 + (t & 1));   // wait: consumers done with this buffer
            float* base = smemDyn + (t & 1) * (2 * KT * KSTR);
            float* row  = base + isV * (KT * KSTR) + pl * KSTR;
            float4 z4 = make_float4(0.f, 0.f, 0.f, 0.f);
#pragma unroll
            for (int i = 0; i < 16; i++) ((float4*)row)[i] = z4;

            int p = k0 + t * KT + pl;
            bool valid = (p < k1);
            int pp = valid ? p : 0;
            float la  = luv[pp];
            float lgg = luv[PIX + pp];
            float lbb = luv[2*PIX + pp];
            float x, wgt;
            if (!isV) {
                float iy = luv[3*PIX + pp];
                if (c == 0)      x = la - lgg;
                else if (c == 1) x = lgg - la;
                else             x = lbb - la;
                wgt = valid ? iy * cw : 0.f;   // invalid pixel: all-zero U row
            } else {
                if (c == 0)      x = la - lbb;
                else if (c == 1) x = lgg - lbb;
                else             x = lbb - lgg;
                wgt = 1.0f;
            }
            int cb = __float2int_rn((x + 3.0f) * 10.0f);
            cb = max(0, min(60, cb));
            float d = x - (-3.0f + 0.1f * (float)cb);
            float fc0 = __expf(-d * d * inv2) * wgt;
            float rup = __expf(( 0.2f * d - 0.01f) * inv2);
            float sdn = __expf((-0.2f * d - 0.01f) * inv2);
            row[cb] = fc0;
            float f = fc0, rr = rup;
#pragma unroll
            for (int j = 1; j <= 16; j++) {
                f *= rr; rr *= q;
                int b2 = cb + j;
                if (b2 <= 60) row[b2] = f;
            }
            f = fc0; rr = sdn;
#pragma unroll
            for (int j = 1; j <= 16; j++) {
                f *= rr; rr *= q;
                int b2 = cb - j;
                if (b2 >= 0) row[b2] = f;
            }
            bar_arrive_n(1 + (t & 1));             // signal: buffer full
        }
    } else {
        int lx = tid - 128;             // 0..127
        int tx = lx & 15;               // v: bins tx*4 .. tx*4+3
        int ty = lx >> 4;               // u: bins ty*8 .. ty*8+7

        ull acc[8][2];
#pragma unroll
        for (int a = 0; a < 8; a++) { acc[a][0] = 0ULL; acc[a][1] = 0ULL; }

        for (int t = 0; t < T; t++) {
            bar_sync_n(1 + (t & 1));               // wait: buffer full
            const float* base = smemDyn + (t & 1) * (2 * KT * KSTR);
            const float* bufU = base;
            const float* bufV = base + KT * KSTR;
#pragma unroll 2
            for (int k = 0; k < KT; k++) {
                const float4* Ur = (const float4*)(bufU + k * KSTR + ty * 8);
                float4 Ua = Ur[0], Ub = Ur[1];
                ulonglong2 V = *(const ulonglong2*)(bufV + k * KSTR + tx * 4);
                ull up[8];
                up[0] = pack2(Ua.x, Ua.x); up[1] = pack2(Ua.y, Ua.y);
                up[2] = pack2(Ua.z, Ua.z); up[3] = pack2(Ua.w, Ua.w);
                up[4] = pack2(Ub.x, Ub.x); up[5] = pack2(Ub.y, Ub.y);
                up[6] = pack2(Ub.z, Ub.z); up[7] = pack2(Ub.w, Ub.w);
#pragma unroll
                for (int a = 0; a < 8; a++) {
                    ffma2(acc[a][0], up[a], V.x);
                    ffma2(acc[a][1], up[a], V.y);
                }
            }
            bar_arrive_n(3 + (t & 1));             // signal: buffer empty
        }

        float* out = &g_hist_part[ks][(size_t)b * E_HIST + c * HB * HB];
#pragma unroll
        for (int a = 0; a < 8; a++) {
            int iu = ty * 8 + a;
            if (iu >= HB) continue;
#pragma unroll
            for (int j = 0; j < 2; j++) {
                float lo, hi;
                unpack2(acc[a][j], lo, hi);
                int iv = tx * 4 + 2 * j;
                if (iv < HB)     out[iu * HB + iv]     = lo;
                if (iv + 1 < HB) out[iu * HB + iv + 1] = hi;
            }
        }
    }
}

// ============================================================
// conv1: [B,3,61,61] -> [B,128,29,29], 5x5 s2, relu.
// SPLITK partial-sum + normalization total folded into the load phase.
// ============================================================
__global__ void conv1_kernel(const float* __restrict__ w, const float* __restrict__ bias)
{
    int octile = blockIdx.x;   // 0..7
    int b      = blockIdx.y;
    __shared__ __align__(16) float sInE[3][61][32];
    __shared__ __align__(16) float sInO[3][61][32];
    __shared__ __align__(16) float sW[1200];   // [ic][tap25][ocl16]
    __shared__ float sRed[512];
    int tx = threadIdx.x;      // 0..28
    int ty = threadIdx.y;      // 0..14
    int tid = ty * 29 + tx;    // 0..434

    float lsum = 0.f;
    for (int i = tid; i < E_HIST; i += 435) {
        float h = 0.f;
#pragma unroll
        for (int s = 0; s < SPLITK; s++) h += g_hist_part[s][b * E_HIST + i];
        int ic = i / 3721; int pos = i - ic * 3721;
        int y = pos / 61;  int x = pos - y * 61;
        if (x & 1) sInO[ic][y][x >> 1] = h;
        else       sInE[ic][y][x >> 1] = h;
        lsum += h;
    }
    for (int i = tid; i < 1200; i += 435) {
        int ocl = i & 15; int rest = i >> 4;
        sW[i] = w[(size_t)(octile * 16 + ocl) * 75 + rest];
    }
    sRed[tid] = lsum;
    if (tid < 77) sRed[435 + tid] = 0.f;
    __syncthreads();
    for (int s = 256; s > 0; s >>= 1) {
        if (tid < s) sRed[tid] += sRed[tid + s];
        __syncthreads();
    }
    float inv = 1.0f / (sRed[0] + 1e-6f);

    ull acc[2][8];
#pragma unroll
    for (int p = 0; p < 2; p++)
#pragma unroll
        for (int t = 0; t < 8; t++) acc[p][t] = 0ULL;

    int r1 = min(ty + 15, 28);

#pragma unroll 1
    for (int ic = 0; ic < 3; ic++) {
#pragma unroll
        for (int ky = 0; ky < 5; ky++)
#pragma unroll
            for (int kx = 0; kx < 5; kx++) {
                int xi = tx + (kx >> 1);
                const float (*P)[32] = (kx & 1) ? sInO[ic] : sInE[ic];
                float v0 = P[2 * ty + ky][xi];
                float v1 = P[2 * r1 + ky][xi];
                ull p0 = pack2(v0, v0);
                ull p1 = pack2(v1, v1);
                const ulonglong2* wk = (const ulonglong2*)&sW[(ic * 25 + ky * 5 + kx) * 16];
                ulonglong2 wa = wk[0], wb = wk[1];
                ffma2(acc[0][0], p0, wa.x); ffma2(acc[0][1], p0, wa.y);
                ffma2(acc[0][2], p0, wb.x); ffma2(acc[0][3], p0, wb.y);
                ffma2(acc[1][0], p1, wa.x); ffma2(acc[1][1], p1, wa.y);
                ffma2(acc[1][2], p1, wb.x); ffma2(acc[1][3], p1, wb.y);
                ulonglong2 wc = wk[2], wd = wk[3];
                ffma2(acc[0][4], p0, wc.x); ffma2(acc[0][5], p0, wc.y);
                ffma2(acc[0][6], p0, wd.x); ffma2(acc[0][7], p0, wd.y);
                ffma2(acc[1][4], p1, wc.x); ffma2(acc[1][5], p1, wc.y);
                ffma2(acc[1][6], p1, wd.x); ffma2(acc[1][7], p1, wd.y);
            }
    }

#pragma unroll
    for (int p = 0; p < 2; p++) {
        int oy = ty + p * 15;
        if (oy > 28) continue;
#pragma unroll
        for (int t = 0; t < 8; t++) {
            float lo, hi;
            unpack2(acc[p][t], lo, hi);
            int oc = octile * 16 + 2 * t;
            g_c1[((size_t)(b * 128 + oc) * 29 + oy) * 29 + tx]     = fmaxf(bias[oc]     + inv * lo, 0.f);
            g_c1[((size_t)(b * 128 + oc + 1) * 29 + oy) * 29 + tx] = fmaxf(bias[oc + 1] + inv * hi, 0.f);
        }
    }
}

// ============================================================
// conv2: [B,128,29,29] -> partials [4][B,256,14,14], 3x3 s2
// ============================================================
__global__ void conv2_kernel(const float* __restrict__ w)
{
    int octile = blockIdx.x;   // 0..7 (32 oc)
    int b      = blockIdx.y;
    int ks     = blockIdx.z;   // 0..3 (ic chunk of 32)
    __shared__ __align__(16) float sInE[8][29][16];
    __shared__ __align__(16) float sInO[8][29][16];
    __shared__ __align__(16) float sW[8 * 9 * 32];
    int tx = threadIdx.x;      // 0..13
    int ty = threadIdx.y;      // 0..6
    int z  = threadIdx.z;      // 0..1
    int tid = (z * 7 + ty) * 14 + tx;  // 0..195

    ull acc[2][8];
#pragma unroll
    for (int p = 0; p < 2; p++)
#pragma unroll
        for (int t = 0; t < 8; t++) acc[p][t] = 0ULL;

    for (int s = 0; s < 4; s++) {
        int icg = ks * 32 + s * 8;
        __syncthreads();
        for (int i = tid; i < 8 * 841; i += 196) {
            int ic = i / 841; int pos = i - ic * 841;
            int y = pos / 29; int x = pos - y * 29;
            float v = g_c1[(size_t)(b * 128 + icg) * 841 + i];
            if (x & 1) sInO[ic][y][x >> 1] = v;
            else       sInE[ic][y][x >> 1] = v;
        }
        for (int i = tid; i < 2304; i += 196) {
            int ocl = i & 31;
            int k   = (i >> 5) % 9;
            int ic  = i / 288;
            sW[i] = w[((size_t)(octile * 32 + ocl) * 128 + icg + ic) * 9 + k];
        }
        __syncthreads();
#pragma unroll
        for (int ic = 0; ic < 8; ic++) {
            const float* wp = &sW[ic * 288 + z * 16];
#pragma unroll
            for (int ky = 0; ky < 3; ky++)
#pragma unroll
                for (int kx = 0; kx < 3; kx++) {
                    int xi = tx + (kx >> 1);
                    const float (*P)[16] = (kx & 1) ? sInO[ic] : sInE[ic];
                    float v0 = P[2 * ty + ky][xi];
                    float v1 = P[2 * ty + ky + 14][xi];
                    ull p0 = pack2(v0, v0);
                    ull p1 = pack2(v1, v1);
                    const ulonglong2* wk = (const ulonglong2*)(wp + (ky * 3 + kx) * 32);
                    ulonglong2 wa = wk[0], wb = wk[1];
                    ffma2(acc[0][0], p0, wa.x); ffma2(acc[0][1], p0, wa.y);
                    ffma2(acc[0][2], p0, wb.x); ffma2(acc[0][3], p0, wb.y);
                    ffma2(acc[1][0], p1, wa.x); ffma2(acc[1][1], p1, wa.y);
                    ffma2(acc[1][2], p1, wb.x); ffma2(acc[1][3], p1, wb.y);
                    ulonglong2 wc = wk[2], wd = wk[3];
                    ffma2(acc[0][4], p0, wc.x); ffma2(acc[0][5], p0, wc.y);
                    ffma2(acc[0][6], p0, wd.x); ffma2(acc[0][7], p0, wd.y);
                    ffma2(acc[1][4], p1, wc.x); ffma2(acc[1][5], p1, wc.y);
                    ffma2(acc[1][6], p1, wd.x); ffma2(acc[1][7], p1, wd.y);
                }
        }
    }
    float* outp = &g_c2p[ks][(size_t)b * C2_PER];
#pragma unroll
    for (int p = 0; p < 2; p++) {
        int oy = ty + p * 7;
#pragma unroll
        for (int t = 0; t < 8; t++) {
            float lo, hi;
            unpack2(acc[p][t], lo, hi);
            int oc = octile * 32 + z * 16 + 2 * t;
            outp[((size_t)oc * 14 + oy) * 14 + tx]       = lo;
            outp[((size_t)(oc + 1) * 14 + oy) * 14 + tx] = hi;
        }
    }
}

__global__ void conv2_reduce_kernel(const float* __restrict__ bias)
{
    int idx = blockIdx.x * 256 + threadIdx.x;
    if (idx >= BATCH * C2_PER) return;
    int within = idx % C2_PER;
    int oc = within / 196;
    float s = bias[oc];
#pragma unroll
    for (int k = 0; k < 4; k++) s += g_c2p[k][idx];
    g_c2[idx] = fmaxf(s, 0.f);
}

// ============================================================
// conv3: [B,256,14,14] -> partials [4][B,512,13,13], 2x2 s1
// ============================================================
__global__ void conv3_kernel(const float* __restrict__ w)
{
    int octile = blockIdx.x;   // 0..15
    int b      = blockIdx.y;
    int ks     = blockIdx.z;   // 0..3 (ic chunk of 64)
    __shared__ __align__(16) float sIn[16 * 210];
    __shared__ __align__(16) float sW[16 * 4 * 32];
    int tx = threadIdx.x;      // 0..12
    int ty = threadIdx.y;      // 0..6
    int z  = threadIdx.z;      // 0..1
    int tid = (z * 7 + ty) * 13 + tx;  // 0..181

    for (int i = tid; i < 16 * 210; i += 182) sIn[i] = 0.f;

    ull acc[2][8];
#pragma unroll
    for (int p = 0; p < 2; p++)
#pragma unroll
        for (int t = 0; t < 8; t++) acc[p][t] = 0ULL;

    for (int s = 0; s < 4; s++) {
        int icg = ks * 64 + s * 16;
        __syncthreads();
        for (int i = tid; i < 16 * 196; i += 182) {
            int icl = i / 196, pos = i - icl * 196;
            sIn[icl * 210 + pos] = g_c2[(size_t)(b * 256 + icg) * 196 + i];
        }
        for (int i = tid; i < 2048; i += 182) {
            int ocl = i & 31;
            int k   = (i >> 5) & 3;
            int ic  = i >> 7;
            sW[i] = w[((size_t)(octile * 32 + ocl) * 256 + icg + ic) * 4 + k];
        }
        __syncthreads();
#pragma unroll
        for (int ic = 0; ic < 16; ic++) {
            const float* ip = &sIn[ic * 210 + ty * 14 + tx];
            const float* wp = &sW[ic * 128 + z * 16];
#pragma unroll
            for (int ky = 0; ky < 2; ky++)
#pragma unroll
                for (int kx = 0; kx < 2; kx++) {
                    float v0 = ip[ky * 14 + kx];
                    float v1 = ip[ky * 14 + kx + 98];
                    ull p0 = pack2(v0, v0);
                    ull p1 = pack2(v1, v1);
                    const ulonglong2* wk = (const ulonglong2*)(wp + (ky * 2 + kx) * 32);
                    ulonglong2 wa = wk[0], wb = wk[1];
                    ffma2(acc[0][0], p0, wa.x); ffma2(acc[0][1], p0, wa.y);
                    ffma2(acc[0][2], p0, wb.x); ffma2(acc[0][3], p0, wb.y);
                    ffma2(acc[1][0], p1, wa.x); ffma2(acc[1][1], p1, wa.y);
                    ffma2(acc[1][2], p1, wb.x); ffma2(acc[1][3], p1, wb.y);
                    ulonglong2 wc = wk[2], wd = wk[3];
                    ffma2(acc[0][4], p0, wc.x); ffma2(acc[0][5], p0, wc.y);
                    ffma2(acc[0][6], p0, wd.x); ffma2(acc[0][7], p0, wd.y);
                    ffma2(acc[1][4], p1, wc.x); ffma2(acc[1][5], p1, wc.y);
                    ffma2(acc[1][6], p1, wd.x); ffma2(acc[1][7], p1, wd.y);
                }
        }
    }
    float* outp = &g_c3p[ks][(size_t)b * C3_PER];
#pragma unroll
    for (int p = 0; p < 2; p++) {
        int oy = ty + p * 7;
        if (oy > 12) continue;
#pragma unroll
        for (int t = 0; t < 8; t++) {
            float lo, hi;
            unpack2(acc[p][t], lo, hi);
            int oc = octile * 32 + z * 16 + 2 * t;
            outp[((size_t)oc * 13 + oy) * 13 + tx]       = lo;
            outp[((size_t)(oc + 1) * 13 + oy) * 13 + tx] = hi;
        }
    }
}

__global__ void conv3_reduce_kernel(const float* __restrict__ bias)
{
    int idx = blockIdx.x * 256 + threadIdx.x;
    if (idx >= BATCH * C3_PER) return;
    int within = idx % C3_PER;
    int oc = within / 169;
    float s = bias[oc];
#pragma unroll
    for (int k = 0; k < 4; k++) s += g_c3p[k][idx];
    g_c3[idx] = fmaxf(s, 0.f);
}

// ============================================================
// fc: [B, 86528] @ W[OUT, 86528]^T -> abs
// ============================================================
__global__ void fc_kernel(const float* __restrict__ w, int OUT)
{
    int o = blockIdx.x % OUT;
    int b = blockIdx.x / OUT;
    int tid = threadIdx.x;   // 256
    const float4* a  = (const float4*)&g_c3[(size_t)b * C3_PER];
    const float4* wv = (const float4*)(w + (size_t)o * C3_PER);
    float s = 0.f;
    for (int i = tid; i < C3_PER / 4; i += 256) {
        float4 x = a[i], y = wv[i];
        s += x.x*y.x + x.y*y.y + x.z*y.z + x.w*y.w;
    }
    __shared__ float red[256];
    red[tid] = s;
    __syncthreads();
    for (int st = 128; st > 0; st >>= 1) {
        if (tid < st) red[tid] += red[tid + st];
        __syncthreads();
    }
    if (tid == 0) g_fc[b * OUT + o] = fabsf(red[0]);
}

// ============================================================
__global__ void matrix_kernel()
{
    int b = threadIdx.x;
    if (b >= BATCH) return;
    float v[9];
#pragma unroll
    for (int k = 0; k < 9; k++) v[k] = g_fc[b * 9 + k];
    float m[3][3];
#pragma unroll
    for (int i = 0; i < 3; i++)
#pragma unroll
        for (int j = 0; j < 3; j++) m[i][j] = v[j * 3 + i];
    float n = 0.f;
#pragma unroll
    for (int i = 0; i < 3; i++) {
        float rs = fabsf(m[i][0]) + fabsf(m[i][1]) + fabsf(m[i][2]);
        n = fmaxf(n, rs);
    }
    n += 1e-4f;
    float inv_n = 1.0f / n;
#pragma unroll
    for (int i = 0; i < 3; i++)
#pragma unroll
        for (int j = 0; j < 3; j++) {
            m[i][j] *= inv_n;
            g_m[b * 9 + i * 3 + j] = m[i][j];
        }
    float c00 = m[1][1]*m[2][2] - m[1][2]*m[2][1];
    float c01 = m[1][0]*m[2][2] - m[1][2]*m[2][0];
    float c02 = m[1][0]*m[2][1] - m[1][1]*m[2][0];
    float det = m[0][0]*c00 - m[0][1]*c01 + m[0][2]*c02;
    float id = 1.0f / det;
    g_minv[b*9 + 0] =  c00 * id;
    g_minv[b*9 + 1] = (m[0][2]*m[2][1] - m[0][1]*m[2][2]) * id;
    g_minv[b*9 + 2] = (m[0][1]*m[1][2] - m[0][2]*m[1][1]) * id;
    g_minv[b*9 + 3] = -c01 * id;
    g_minv[b*9 + 4] = (m[0][0]*m[2][2] - m[0][2]*m[2][0]) * id;
    g_minv[b*9 + 5] = (m[0][2]*m[1][0] - m[0][0]*m[1][2]) * id;
    g_minv[b*9 + 6] =  c02 * id;
    g_minv[b*9 + 7] = (m[0][1]*m[2][0] - m[0][0]*m[2][1]) * id;
    g_minv[b*9 + 8] = (m[0][0]*m[1][1] - m[0][1]*m[1][0]) * id;
}

__global__ void final_kernel(float* __restrict__ out)
{
    int b = threadIdx.x;
    if (b >= BATCH) return;
    float il[3];
#pragma unroll
    for (int j = 0; j < 3; j++) il[j] = g_fc[b * 3 + j];
#pragma unroll
    for (int i = 0; i < 3; i++)
        out[b * 3 + i] = g_minv[b*9 + i*3 + 0] * il[0]
                       + g_minv[b*9 + i*3 + 1] * il[1]
                       + g_minv[b*9 + i*3 + 2] * il[2];
}

// ============================================================
extern "C" void kernel_launch(void* const* d_in, const int* in_sizes, int n_in,
                              void* d_out, int out_size)
{
    const float* image = (const float*)d_in[0];
    const float* su_s  = (const float*)d_in[1];
    const float* sv_s  = (const float*)d_in[2];
    const float* c_s   = (const float*)d_in[3];
    const float* w1_s  = (const float*)d_in[4];
    const float* b1_s  = (const float*)d_in[5];
    const float* w2_s  = (const float*)d_in[6];
    const float* b2_s  = (const float*)d_in[7];
    const float* w3_s  = (const float*)d_in[8];
    const float* b3_s  = (const float*)d_in[9];
    const float* fc_s  = (const float*)d_in[10];
    const float* su_i  = (const float*)d_in[11];
    const float* sv_i  = (const float*)d_in[12];
    const float* c_i   = (const float*)d_in[13];
    const float* w1_i  = (const float*)d_in[14];
    const float* b1_i  = (const float*)d_in[15];
    const float* w2_i  = (const float*)d_in[16];
    const float* b2_i  = (const float*)d_in[17];
    const float* w3_i  = (const float*)d_in[18];
    const float* b3_i  = (const float*)d_in[19];
    const float* fc_i  = (const float*)d_in[20];

    static int smem_set = 0;
    if (!smem_set) {
        cudaFuncSetAttribute(hist_kernel,
                             cudaFuncAttributeMaxDynamicSharedMemorySize, HIST_SMEM);
        smem_set = 1;
    }

    dim3 cb1(29, 15), cb2(14, 7, 2), cb3(13, 7, 2);
    dim3 cg1(8, BATCH), cg2(8, BATCH, 4), cg3(16, BATCH, 4);
    int prep_blocks = (BATCH * PIX + 255) / 256;
    int c2r_blocks = (BATCH * C2_PER + 255) / 256;
    int c3r_blocks = (BATCH * C3_PER + 255) / 256;

    // ---- sensor branch ----
    prep_kernel<<<prep_blocks, 256>>>(image, 0);
    zero_bsum_kernel<<<1, 128>>>();          // capture-slot alignment
    zero_fc_kernel<<<1, 160>>>();            // capture-slot alignment
    hist_kernel<<<BATCH * 3 * SPLITK, 256, HIST_SMEM>>>(su_s, sv_s, c_s);  // 4th -> ncu
    conv1_kernel<<<cg1, cb1>>>(w1_s, b1_s);
    conv2_kernel<<<cg2, cb2>>>(w2_s);
    conv2_reduce_kernel<<<c2r_blocks, 256>>>(b2_s);
    conv3_kernel<<<cg3, cb3>>>(w3_s);
    conv3_reduce_kernel<<<c3r_blocks, 256>>>(b3_s);
    fc_kernel<<<BATCH * 9, 256>>>(fc_s, 9);
    matrix_kernel<<<1, 32>>>();

    // ---- illuminant branch ----
    prep_kernel<<<prep_blocks, 256>>>(image, 1);
    hist_kernel<<<BATCH * 3 * SPLITK, 256, HIST_SMEM>>>(su_i, sv_i, c_i);
    conv1_kernel<<<cg1, cb1>>>(w1_i, b1_i);
    conv2_kernel<<<cg2, cb2>>>(w2_i);
    conv2_reduce_kernel<<<c2r_blocks, 256>>>(b2_i);
    conv3_kernel<<<cg3, cb3>>>(w3_i);
    conv3_reduce_kernel<<<c3r_blocks, 256>>>(b3_i);
    fc_kernel<<<BATCH * 3, 256>>>(fc_i, 3);
    final_kernel<<<1, 32>>>((float*)d_out);
}

// round 15
// speedup vs baseline: 1.1652x; 1.0214x over previous
#include <cuda_runtime.h>
#include <math.h>

#define BATCH 16
#define PIX   22500          // 150*150
#define HB    61
#define SPLITK 9
#define KT    64
#define KCH   2560           // 9*2560 = 23040 >= 22500, multiple of KT

#define KSTR  68             // padded row stride (floats)
#define HIST_SMEM (4 * KT * KSTR * 4)   // 2 buffers x (U+V planes) = 69632 B

#define E_HIST (3*HB*HB)     // 11163
#define C1_PER (128*29*29)   // 107648
#define C2_PER (256*14*14)   // 50176
#define C3_PER (512*13*13)   // 86528
#define FC_KC  16            // fc K-chunks
#define FC_CH4 (C3_PER / 4 / FC_KC)   // 1352 float4 per chunk

typedef unsigned long long ull;

__device__ __forceinline__ ull pack2(float x, float y) {
    ull r; asm("mov.b64 %0, {%1, %2};" : "=l"(r) : "f"(x), "f"(y)); return r;
}
__device__ __forceinline__ void unpack2(ull v, float& x, float& y) {
    asm("mov.b64 {%0, %1}, %2;" : "=f"(x), "=f"(y) : "l"(v));
}
__device__ __forceinline__ void ffma2(ull& d, ull a, ull b) {
    asm("fma.rn.f32x2 %0, %1, %2, %3;" : "=l"(d) : "l"(a), "l"(b), "l"(d));
}
__device__ __forceinline__ void bar_sync_n(int id) {
    asm volatile("bar.sync %0, 256;" :: "r"(id) : "memory");
}
__device__ __forceinline__ void bar_arrive_n(int id) {
    asm volatile("bar.arrive %0, 256;" :: "r"(id) : "memory");
}

// -------- scratch --------
__device__ float g_luv[BATCH*4*PIX];
__device__ float g_hist_part[SPLITK][BATCH*E_HIST];
__device__ float g_c1[BATCH*C1_PER];
__device__ float g_c2p[4][BATCH*C2_PER];
__device__ float g_c2[BATCH*C2_PER];
__device__ float g_c3p[4][BATCH*C3_PER];
__device__ float g_c3[BATCH*C3_PER];
__device__ float g_fc_part[FC_KC][BATCH*9];
__device__ float g_m[BATCH*9];
__device__ float g_minv[BATCH*9];

// ============================================================
// prep: image -> (lr,lg,lb,iy). mode 1: apply g_m first
// ============================================================
__global__ void prep_kernel(const float* __restrict__ img, int mapped)
{
    int idx = blockIdx.x * 256 + threadIdx.x;
    if (idx >= BATCH * PIX) return;
    int b = idx / PIX;
    int p = idx - b * PIX;
    float r  = img[(size_t)(b * 3 + 0) * PIX + p];
    float g  = img[(size_t)(b * 3 + 1) * PIX + p];
    float bl = img[(size_t)(b * 3 + 2) * PIX + p];
    if (mapped) {
        const float* M = &g_m[b * 9];
        float r2  = M[0]*r + M[1]*g + M[2]*bl;
        float g2  = M[3]*r + M[4]*g + M[5]*bl;
        float bl2 = M[6]*r + M[7]*g + M[8]*bl;
        r = r2; g = g2; bl = bl2;
    }
    r  = fminf(fmaxf(r, 0.f), 1.f);
    g  = fminf(fmaxf(g, 0.f), 1.f);
    bl = fminf(fmaxf(bl, 0.f), 1.f);
    float iy = sqrtf(r*r + g*g + bl*bl);
    g_luv[(size_t)(b*4 + 0)*PIX + p] = logf(r + 1e-6f);
    g_luv[(size_t)(b*4 + 1)*PIX + p] = logf(g + 1e-6f);
    g_luv[(size_t)(b*4 + 2)*PIX + p] = logf(bl + 1e-6f);
    g_luv[(size_t)(b*4 + 3)*PIX + p] = iy;
}

// ============================================================
// Histogram: warp-specialized producer/consumer with double buffering,
// split named barriers (R14 structure — best measured variant).
// ============================================================
__global__ void __launch_bounds__(256, 3)
hist_kernel(const float* __restrict__ su,
            const float* __restrict__ sv,
            const float* __restrict__ cpar)
{
    extern __shared__ __align__(16) float smemDyn[];   // [2][2][KT*KSTR]

    int blk = blockIdx.x;
    int ks  = blk % SPLITK;
    int bc  = blk / SPLITK;
    int c   = bc % 3;
    int b   = bc / 3;

    float sg_u = su[c], sg_v = sv[c];
    float inv_u2 = 1.0f / (sg_u * sg_u);
    float inv_v2 = 1.0f / (sg_v * sg_v);
    float cw = cpar[c];

    int tid = threadIdx.x;          // 256
    bool is_builder = (tid < 128);

    int k0 = ks * KCH;
    int k1 = min(k0 + KCH, PIX);
    int T  = (k1 - k0 + KT - 1) / KT;
    const float* luv = g_luv + (size_t)b * 4 * PIX;

    if (is_builder) {
        int pl  = tid & 63;
        int isV = (tid >> 6) & 1;
        float inv2 = isV ? inv_v2 : inv_u2;
        float q    = __expf(-0.02f * inv2);

        for (int t = 0; t < T; t++) {
            if (t >= 2) bar_sync_n(3 + (t & 1));
            float* base = smemDyn + (t & 1) * (2 * KT * KSTR);
            float* row  = base + isV * (KT * KSTR) + pl * KSTR;
            float4 z4 = make_float4(0.f, 0.f, 0.f, 0.f);
#pragma unroll
            for (int i = 0; i < 16; i++) ((float4*)row)[i] = z4;

            int p = k0 + t * KT + pl;
            bool valid = (p < k1);
            int pp = valid ? p : 0;
            float la  = luv[pp];
            float lgg = luv[PIX + pp];
            float lbb = luv[2*PIX + pp];
            float x, wgt;
            if (!isV) {
                float iy = luv[3*PIX + pp];
                if (c == 0)      x = la - lgg;
                else if (c == 1) x = lgg - la;
                else             x = lbb - la;
                wgt = valid ? iy * cw : 0.f;
            } else {
                if (c == 0)      x = la - lbb;
                else if (c == 1) x = lgg - lbb;
                else             x = lbb - lgg;
                wgt = 1.0f;
            }
            int cb = __float2int_rn((x + 3.0f) * 10.0f);
            cb = max(0, min(60, cb));
            float d = x - (-3.0f + 0.1f * (float)cb);
            float fc0 = __expf(-d * d * inv2) * wgt;
            float rup = __expf(( 0.2f * d - 0.01f) * inv2);
            float sdn = __expf((-0.2f * d - 0.01f) * inv2);
            row[cb] = fc0;
            float f = fc0, rr = rup;
#pragma unroll
            for (int j = 1; j <= 16; j++) {
                f *= rr; rr *= q;
                int b2 = cb + j;
                if (b2 <= 60) row[b2] = f;
            }
            f = fc0; rr = sdn;
#pragma unroll
            for (int j = 1; j <= 16; j++) {
                f *= rr; rr *= q;
                int b2 = cb - j;
                if (b2 >= 0) row[b2] = f;
            }
            bar_arrive_n(1 + (t & 1));
        }
    } else {
        int lx = tid - 128;
        int tx = lx & 15;
        int ty = lx >> 4;

        ull acc[8][2];
#pragma unroll
        for (int a = 0; a < 8; a++) { acc[a][0] = 0ULL; acc[a][1] = 0ULL; }

        for (int t = 0; t < T; t++) {
            bar_sync_n(1 + (t & 1));
            const float* base = smemDyn + (t & 1) * (2 * KT * KSTR);
            const float* bufU = base;
            const float* bufV = base + KT * KSTR;
#pragma unroll 2
            for (int k = 0; k < KT; k++) {
                const float4* Ur = (const float4*)(bufU + k * KSTR + ty * 8);
                float4 Ua = Ur[0], Ub = Ur[1];
                ulonglong2 V = *(const ulonglong2*)(bufV + k * KSTR + tx * 4);
                ull up[8];
                up[0] = pack2(Ua.x, Ua.x); up[1] = pack2(Ua.y, Ua.y);
                up[2] = pack2(Ua.z, Ua.z); up[3] = pack2(Ua.w, Ua.w);
                up[4] = pack2(Ub.x, Ub.x); up[5] = pack2(Ub.y, Ub.y);
                up[6] = pack2(Ub.z, Ub.z); up[7] = pack2(Ub.w, Ub.w);
#pragma unroll
                for (int a = 0; a < 8; a++) {
                    ffma2(acc[a][0], up[a], V.x);
                    ffma2(acc[a][1], up[a], V.y);
                }
            }
            bar_arrive_n(3 + (t & 1));
        }

        float* out = &g_hist_part[ks][(size_t)b * E_HIST + c * HB * HB];
#pragma unroll
        for (int a = 0; a < 8; a++) {
            int iu = ty * 8 + a;
            if (iu >= HB) continue;
#pragma unroll
            for (int j = 0; j < 2; j++) {
                float lo, hi;
                unpack2(acc[a][j], lo, hi);
                int iv = tx * 4 + 2 * j;
                if (iv < HB)     out[iu * HB + iv]     = lo;
                if (iv + 1 < HB) out[iu * HB + iv + 1] = hi;
            }
        }
    }
}

// ============================================================
// conv1: SPLITK partial-sum + normalization total folded into load phase.
// ============================================================
__global__ void conv1_kernel(const float* __restrict__ w, const float* __restrict__ bias)
{
    int octile = blockIdx.x;   // 0..7
    int b      = blockIdx.y;
    __shared__ __align__(16) float sInE[3][61][32];
    __shared__ __align__(16) float sInO[3][61][32];
    __shared__ __align__(16) float sW[1200];
    __shared__ float sRed[512];
    int tx = threadIdx.x;      // 0..28
    int ty = threadIdx.y;      // 0..14
    int tid = ty * 29 + tx;    // 0..434

    float lsum = 0.f;
    for (int i = tid; i < E_HIST; i += 435) {
        float h = 0.f;
#pragma unroll
        for (int s = 0; s < SPLITK; s++) h += g_hist_part[s][b * E_HIST + i];
        int ic = i / 3721; int pos = i - ic * 3721;
        int y = pos / 61;  int x = pos - y * 61;
        if (x & 1) sInO[ic][y][x >> 1] = h;
        else       sInE[ic][y][x >> 1] = h;
        lsum += h;
    }
    for (int i = tid; i < 1200; i += 435) {
        int ocl = i & 15; int rest = i >> 4;
        sW[i] = w[(size_t)(octile * 16 + ocl) * 75 + rest];
    }
    sRed[tid] = lsum;
    if (tid < 77) sRed[435 + tid] = 0.f;
    __syncthreads();
    for (int s = 256; s > 0; s >>= 1) {
        if (tid < s) sRed[tid] += sRed[tid + s];
        __syncthreads();
    }
    float inv = 1.0f / (sRed[0] + 1e-6f);

    ull acc[2][8];
#pragma unroll
    for (int p = 0; p < 2; p++)
#pragma unroll
        for (int t = 0; t < 8; t++) acc[p][t] = 0ULL;

    int r1 = min(ty + 15, 28);

#pragma unroll 1
    for (int ic = 0; ic < 3; ic++) {
#pragma unroll
        for (int ky = 0; ky < 5; ky++)
#pragma unroll
            for (int kx = 0; kx < 5; kx++) {
                int xi = tx + (kx >> 1);
                const float (*P)[32] = (kx & 1) ? sInO[ic] : sInE[ic];
                float v0 = P[2 * ty + ky][xi];
                float v1 = P[2 * r1 + ky][xi];
                ull p0 = pack2(v0, v0);
                ull p1 = pack2(v1, v1);
                const ulonglong2* wk = (const ulonglong2*)&sW[(ic * 25 + ky * 5 + kx) * 16];
                ulonglong2 wa = wk[0], wb = wk[1];
                ffma2(acc[0][0], p0, wa.x); ffma2(acc[0][1], p0, wa.y);
                ffma2(acc[0][2], p0, wb.x); ffma2(acc[0][3], p0, wb.y);
                ffma2(acc[1][0], p1, wa.x); ffma2(acc[1][1], p1, wa.y);
                ffma2(acc[1][2], p1, wb.x); ffma2(acc[1][3], p1, wb.y);
                ulonglong2 wc = wk[2], wd = wk[3];
                ffma2(acc[0][4], p0, wc.x); ffma2(acc[0][5], p0, wc.y);
                ffma2(acc[0][6], p0, wd.x); ffma2(acc[0][7], p0, wd.y);
                ffma2(acc[1][4], p1, wc.x); ffma2(acc[1][5], p1, wc.y);
                ffma2(acc[1][6], p1, wd.x); ffma2(acc[1][7], p1, wd.y);
            }
    }

#pragma unroll
    for (int p = 0; p < 2; p++) {
        int oy = ty + p * 15;
        if (oy > 28) continue;
#pragma unroll
        for (int t = 0; t < 8; t++) {
            float lo, hi;
            unpack2(acc[p][t], lo, hi);
            int oc = octile * 16 + 2 * t;
            g_c1[((size_t)(b * 128 + oc) * 29 + oy) * 29 + tx]     = fmaxf(bias[oc]     + inv * lo, 0.f);
            g_c1[((size_t)(b * 128 + oc + 1) * 29 + oy) * 29 + tx] = fmaxf(bias[oc + 1] + inv * hi, 0.f);
        }
    }
}

// ============================================================
// conv2: [B,128,29,29] -> partials [4][B,256,14,14], 3x3 s2
// ============================================================
__global__ void conv2_kernel(const float* __restrict__ w)
{
    int octile = blockIdx.x;
    int b      = blockIdx.y;
    int ks     = blockIdx.z;
    __shared__ __align__(16) float sInE[8][29][16];
    __shared__ __align__(16) float sInO[8][29][16];
    __shared__ __align__(16) float sW[8 * 9 * 32];
    int tx = threadIdx.x;
    int ty = threadIdx.y;
    int z  = threadIdx.z;
    int tid = (z * 7 + ty) * 14 + tx;

    ull acc[2][8];
#pragma unroll
    for (int p = 0; p < 2; p++)
#pragma unroll
        for (int t = 0; t < 8; t++) acc[p][t] = 0ULL;

    for (int s = 0; s < 4; s++) {
        int icg = ks * 32 + s * 8;
        __syncthreads();
        for (int i = tid; i < 8 * 841; i += 196) {
            int ic = i / 841; int pos = i - ic * 841;
            int y = pos / 29; int x = pos - y * 29;
            float v = g_c1[(size_t)(b * 128 + icg) * 841 + i];
            if (x & 1) sInO[ic][y][x >> 1] = v;
            else       sInE[ic][y][x >> 1] = v;
        }
        for (int i = tid; i < 2304; i += 196) {
            int ocl = i & 31;
            int k   = (i >> 5) % 9;
            int ic  = i / 288;
            sW[i] = w[((size_t)(octile * 32 + ocl) * 128 + icg + ic) * 9 + k];
        }
        __syncthreads();
#pragma unroll
        for (int ic = 0; ic < 8; ic++) {
            const float* wp = &sW[ic * 288 + z * 16];
#pragma unroll
            for (int ky = 0; ky < 3; ky++)
#pragma unroll
                for (int kx = 0; kx < 3; kx++) {
                    int xi = tx + (kx >> 1);
                    const float (*P)[16] = (kx & 1) ? sInO[ic] : sInE[ic];
                    float v0 = P[2 * ty + ky][xi];
                    float v1 = P[2 * ty + ky + 14][xi];
                    ull p0 = pack2(v0, v0);
                    ull p1 = pack2(v1, v1);
                    const ulonglong2* wk = (const ulonglong2*)(wp + (ky * 3 + kx) * 32);
                    ulonglong2 wa = wk[0], wb = wk[1];
                    ffma2(acc[0][0], p0, wa.x); ffma2(acc[0][1], p0, wa.y);
                    ffma2(acc[0][2], p0, wb.x); ffma2(acc[0][3], p0, wb.y);
                    ffma2(acc[1][0], p1, wa.x); ffma2(acc[1][1], p1, wa.y);
                    ffma2(acc[1][2], p1, wb.x); ffma2(acc[1][3], p1, wb.y);
                    ulonglong2 wc = wk[2], wd = wk[3];
                    ffma2(acc[0][4], p0, wc.x); ffma2(acc[0][5], p0, wc.y);
                    ffma2(acc[0][6], p0, wd.x); ffma2(acc[0][7], p0, wd.y);
                    ffma2(acc[1][4], p1, wc.x); ffma2(acc[1][5], p1, wc.y);
                    ffma2(acc[1][6], p1, wd.x); ffma2(acc[1][7], p1, wd.y);
                }
        }
    }
    float* outp = &g_c2p[ks][(size_t)b * C2_PER];
#pragma unroll
    for (int p = 0; p < 2; p++) {
        int oy = ty + p * 7;
#pragma unroll
        for (int t = 0; t < 8; t++) {
            float lo, hi;
            unpack2(acc[p][t], lo, hi);
            int oc = octile * 32 + z * 16 + 2 * t;
            outp[((size_t)oc * 14 + oy) * 14 + tx]       = lo;
            outp[((size_t)(oc + 1) * 14 + oy) * 14 + tx] = hi;
        }
    }
}

__global__ void conv2_reduce_kernel(const float* __restrict__ bias)
{
    int idx = blockIdx.x * 256 + threadIdx.x;
    if (idx >= BATCH * C2_PER) return;
    int within = idx % C2_PER;
    int oc = within / 196;
    float s = bias[oc];
#pragma unroll
    for (int k = 0; k < 4; k++) s += g_c2p[k][idx];
    g_c2[idx] = fmaxf(s, 0.f);
}

// ============================================================
// conv3: [B,256,14,14] -> partials [4][B,512,13,13], 2x2 s1
// ============================================================
__global__ void conv3_kernel(const float* __restrict__ w)
{
    int octile = blockIdx.x;
    int b      = blockIdx.y;
    int ks     = blockIdx.z;
    __shared__ __align__(16) float sIn[16 * 210];
    __shared__ __align__(16) float sW[16 * 4 * 32];
    int tx = threadIdx.x;
    int ty = threadIdx.y;
    int z  = threadIdx.z;
    int tid = (z * 7 + ty) * 13 + tx;

    for (int i = tid; i < 16 * 210; i += 182) sIn[i] = 0.f;

    ull acc[2][8];
#pragma unroll
    for (int p = 0; p < 2; p++)
#pragma unroll
        for (int t = 0; t < 8; t++) acc[p][t] = 0ULL;

    for (int s = 0; s < 4; s++) {
        int icg = ks * 64 + s * 16;
        __syncthreads();
        for (int i = tid; i < 16 * 196; i += 182) {
            int icl = i / 196, pos = i - icl * 196;
            sIn[icl * 210 + pos] = g_c2[(size_t)(b * 256 + icg) * 196 + i];
        }
        for (int i = tid; i < 2048; i += 182) {
            int ocl = i & 31;
            int k   = (i >> 5) & 3;
            int ic  = i >> 7;
            sW[i] = w[((size_t)(octile * 32 + ocl) * 256 + icg + ic) * 4 + k];
        }
        __syncthreads();
#pragma unroll
        for (int ic = 0; ic < 16; ic++) {
            const float* ip = &sIn[ic * 210 + ty * 14 + tx];
            const float* wp = &sW[ic * 128 + z * 16];
#pragma unroll
            for (int ky = 0; ky < 2; ky++)
#pragma unroll
                for (int kx = 0; kx < 2; kx++) {
                    float v0 = ip[ky * 14 + kx];
                    float v1 = ip[ky * 14 + kx + 98];
                    ull p0 = pack2(v0, v0);
                    ull p1 = pack2(v1, v1);
                    const ulonglong2* wk = (const ulonglong2*)(wp + (ky * 2 + kx) * 32);
                    ulonglong2 wa = wk[0], wb = wk[1];
                    ffma2(acc[0][0], p0, wa.x); ffma2(acc[0][1], p0, wa.y);
                    ffma2(acc[0][2], p0, wb.x); ffma2(acc[0][3], p0, wb.y);
                    ffma2(acc[1][0], p1, wa.x); ffma2(acc[1][1], p1, wa.y);
                    ffma2(acc[1][2], p1, wb.x); ffma2(acc[1][3], p1, wb.y);
                    ulonglong2 wc = wk[2], wd = wk[3];
                    ffma2(acc[0][4], p0, wc.x); ffma2(acc[0][5], p0, wc.y);
                    ffma2(acc[0][6], p0, wd.x); ffma2(acc[0][7], p0, wd.y);
                    ffma2(acc[1][4], p1, wc.x); ffma2(acc[1][5], p1, wc.y);
                    ffma2(acc[1][6], p1, wd.x); ffma2(acc[1][7], p1, wd.y);
                }
        }
    }
    float* outp = &g_c3p[ks][(size_t)b * C3_PER];
#pragma unroll
    for (int p = 0; p < 2; p++) {
        int oy = ty + p * 7;
        if (oy > 12) continue;
#pragma unroll
        for (int t = 0; t < 8; t++) {
            float lo, hi;
            unpack2(acc[p][t], lo, hi);
            int oc = octile * 32 + z * 16 + 2 * t;
            outp[((size_t)oc * 13 + oy) * 13 + tx]       = lo;
            outp[((size_t)(oc + 1) * 13 + oy) * 13 + tx] = hi;
        }
    }
}

__global__ void conv3_reduce_kernel(const float* __restrict__ bias)
{
    int idx = blockIdx.x * 256 + threadIdx.x;
    if (idx >= BATCH * C3_PER) return;
    int within = idx % C3_PER;
    int oc = within / 169;
    float s = bias[oc];
#pragma unroll
    for (int k = 0; k < 4; k++) s += g_c3p[k][idx];
    g_c3[idx] = fmaxf(s, 0.f);
}

// ============================================================
// fc (split-K): grid (FC_KC, 4). Each block: 4 batches x OUT outputs over
// a K/16 slice. Partials to g_fc_part; folded in matrix/final kernels.
// ============================================================
template<int OUT>
__global__ void fc_kernel(const float* __restrict__ w)
{
    int kc = blockIdx.x;       // 0..15
    int bg = blockIdx.y;       // 0..3
    int tid = threadIdx.x;     // 256
    int lane = tid & 31, wid = tid >> 5;
    int base4 = kc * FC_CH4;

    float acc[4][OUT];
#pragma unroll
    for (int bi = 0; bi < 4; bi++)
#pragma unroll
        for (int o = 0; o < OUT; o++) acc[bi][o] = 0.f;

    const float4* act = (const float4*)g_c3;
    const float4* wv4 = (const float4*)w;

    for (int i = tid; i < FC_CH4; i += 256) {
        float4 a[4];
#pragma unroll
        for (int bi = 0; bi < 4; bi++)
            a[bi] = act[(size_t)(bg * 4 + bi) * (C3_PER / 4) + base4 + i];
#pragma unroll
        for (int o = 0; o < OUT; o++) {
            float4 wv = wv4[(size_t)o * (C3_PER / 4) + base4 + i];
#pragma unroll
            for (int bi = 0; bi < 4; bi++)
                acc[bi][o] += a[bi].x * wv.x + a[bi].y * wv.y
                            + a[bi].z * wv.z + a[bi].w * wv.w;
        }
    }

    __shared__ float red[8][4 * OUT];
#pragma unroll
    for (int bi = 0; bi < 4; bi++)
#pragma unroll
        for (int o = 0; o < OUT; o++) {
            float v = acc[bi][o];
#pragma unroll
            for (int s = 16; s > 0; s >>= 1)
                v += __shfl_down_sync(0xffffffffu, v, s);
            if (lane == 0) red[wid][bi * OUT + o] = v;
        }
    __syncthreads();
    if (tid < 4 * OUT) {
        float s = 0.f;
#pragma unroll
        for (int wg = 0; wg < 8; wg++) s += red[wg][tid];
        int bi = tid / OUT, o = tid % OUT;
        g_fc_part[kc][(bg * 4 + bi) * OUT + o] = s;
    }
}

// ============================================================
__global__ void matrix_kernel()
{
    int b = threadIdx.x;
    if (b >= BATCH) return;
    float v[9];
#pragma unroll
    for (int o = 0; o < 9; o++) {
        float s = 0.f;
#pragma unroll
        for (int kc = 0; kc < FC_KC; kc++) s += g_fc_part[kc][b * 9 + o];
        v[o] = fabsf(s);
    }
    float m[3][3];
#pragma unroll
    for (int i = 0; i < 3; i++)
#pragma unroll
        for (int j = 0; j < 3; j++) m[i][j] = v[j * 3 + i];
    float n = 0.f;
#pragma unroll
    for (int i = 0; i < 3; i++) {
        float rs = fabsf(m[i][0]) + fabsf(m[i][1]) + fabsf(m[i][2]);
        n = fmaxf(n, rs);
    }
    n += 1e-4f;
    float inv_n = 1.0f / n;
#pragma unroll
    for (int i = 0; i < 3; i++)
#pragma unroll
        for (int j = 0; j < 3; j++) {
            m[i][j] *= inv_n;
            g_m[b * 9 + i * 3 + j] = m[i][j];
        }
    float c00 = m[1][1]*m[2][2] - m[1][2]*m[2][1];
    float c01 = m[1][0]*m[2][2] - m[1][2]*m[2][0];
    float c02 = m[1][0]*m[2][1] - m[1][1]*m[2][0];
    float det = m[0][0]*c00 - m[0][1]*c01 + m[0][2]*c02;
    float id = 1.0f / det;
    g_minv[b*9 + 0] =  c00 * id;
    g_minv[b*9 + 1] = (m[0][2]*m[2][1] - m[0][1]*m[2][2]) * id;
    g_minv[b*9 + 2] = (m[0][1]*m[1][2] - m[0][2]*m[1][1]) * id;
    g_minv[b*9 + 3] = -c01 * id;
    g_minv[b*9 + 4] = (m[0][0]*m[2][2] - m[0][2]*m[2][0]) * id;
    g_minv[b*9 + 5] = (m[0][2]*m[1][0] - m[0][0]*m[1][2]) * id;
    g_minv[b*9 + 6] =  c02 * id;
    g_minv[b*9 + 7] = (m[0][1]*m[2][0] - m[0][0]*m[2][1]) * id;
    g_minv[b*9 + 8] = (m[0][0]*m[1][1] - m[0][1]*m[1][0]) * id;
}

__global__ void final_kernel(float* __restrict__ out)
{
    int b = threadIdx.x;
    if (b >= BATCH) return;
    float il[3];
#pragma unroll
    for (int j = 0; j < 3; j++) {
        float s = 0.f;
#pragma unroll
        for (int kc = 0; kc < FC_KC; kc++) s += g_fc_part[kc][b * 3 + j];
        il[j] = fabsf(s);
    }
#pragma unroll
    for (int i = 0; i < 3; i++)
        out[b * 3 + i] = g_minv[b*9 + i*3 + 0] * il[0]
                       + g_minv[b*9 + i*3 + 1] * il[1]
                       + g_minv[b*9 + i*3 + 2] * il[2];
}

// ============================================================
extern "C" void kernel_launch(void* const* d_in, const int* in_sizes, int n_in,
                              void* d_out, int out_size)
{
    const float* image = (const float*)d_in[0];
    const float* su_s  = (const float*)d_in[1];
    const float* sv_s  = (const float*)d_in[2];
    const float* c_s   = (const float*)d_in[3];
    const float* w1_s  = (const float*)d_in[4];
    const float* b1_s  = (const float*)d_in[5];
    const float* w2_s  = (const float*)d_in[6];
    const float* b2_s  = (const float*)d_in[7];
    const float* w3_s  = (const float*)d_in[8];
    const float* b3_s  = (const float*)d_in[9];
    const float* fc_s  = (const float*)d_in[10];
    const float* su_i  = (const float*)d_in[11];
    const float* sv_i  = (const float*)d_in[12];
    const float* c_i   = (const float*)d_in[13];
    const float* w1_i  = (const float*)d_in[14];
    const float* b1_i  = (const float*)d_in[15];
    const float* w2_i  = (const float*)d_in[16];
    const float* b2_i  = (const float*)d_in[17];
    const float* w3_i  = (const float*)d_in[18];
    const float* b3_i  = (const float*)d_in[19];
    const float* fc_i  = (const float*)d_in[20];

    static int smem_set = 0;
    if (!smem_set) {
        cudaFuncSetAttribute(hist_kernel,
                             cudaFuncAttributeMaxDynamicSharedMemorySize, HIST_SMEM);
        smem_set = 1;
    }

    dim3 cb1(29, 15), cb2(14, 7, 2), cb3(13, 7, 2);
    dim3 cg1(8, BATCH), cg2(8, BATCH, 4), cg3(16, BATCH, 4);
    dim3 cgfc(FC_KC, 4);
    int prep_blocks = (BATCH * PIX + 255) / 256;
    int c2r_blocks = (BATCH * C2_PER + 255) / 256;
    int c3r_blocks = (BATCH * C3_PER + 255) / 256;

    // ---- sensor branch ----  (conv2 is now the 4th launch -> ncu slot)
    prep_kernel<<<prep_blocks, 256>>>(image, 0);
    hist_kernel<<<BATCH * 3 * SPLITK, 256, HIST_SMEM>>>(su_s, sv_s, c_s);
    conv1_kernel<<<cg1, cb1>>>(w1_s, b1_s);
    conv2_kernel<<<cg2, cb2>>>(w2_s);
    conv2_reduce_kernel<<<c2r_blocks, 256>>>(b2_s);
    conv3_kernel<<<cg3, cb3>>>(w3_s);
    conv3_reduce_kernel<<<c3r_blocks, 256>>>(b3_s);
    fc_kernel<9><<<cgfc, 256>>>(fc_s);
    matrix_kernel<<<1, 32>>>();

    // ---- illuminant branch ----
    prep_kernel<<<prep_blocks, 256>>>(image, 1);
    hist_kernel<<<BATCH * 3 * SPLITK, 256, HIST_SMEM>>>(su_i, sv_i, c_i);
    conv1_kernel<<<cg1, cb1>>>(w1_i, b1_i);
    conv2_kernel<<<cg2, cb2>>>(w2_i);
    conv2_reduce_kernel<<<c2r_blocks, 256>>>(b2_i);
    conv3_kernel<<<cg3, cb3>>>(w3_i);
    conv3_reduce_kernel<<<c3r_blocks, 256>>>(b3_i);
    fc_kernel<3><<<cgfc, 256>>>(fc_i);
    final_kernel<<<1, 32>>>((float*)d_out);
}

// round 16
// speedup vs baseline: 1.3486x; 1.1574x over previous
#include <cuda_runtime.h>
#include <math.h>

#define BATCH 16
#define PIX   22500          // 150*150
#define HB    61
#define SPLITK 9
#define KT    64
#define KCH   2560           // 9*2560 = 23040 >= 22500, multiple of KT

#define KSTR  68             // padded row stride (floats)
#define HIST_SMEM (4 * KT * KSTR * 4)   // 2 buffers x (U+V planes) = 69632 B

#define E_HIST (3*HB*HB)     // 11163
#define C1_PER (128*29*29)   // 107648
#define C1STR  36            // padded even/odd row stride for g_c1L
#define C2_PER (256*14*14)   // 50176
#define C2STR  212           // padded per-channel stride for g_c2
#define C3_PER (512*13*13)   // 86528
#define FC_KC  16            // fc K-chunks
#define FC_CH4 (C3_PER / 4 / FC_KC)   // 1352 float4 per chunk
#define W2T_N  294912        // 8*4*4*8*9*32
#define W3T_N  524288        // 16*4*4*16*4*32

typedef unsigned long long ull;

__device__ __forceinline__ ull pack2(float x, float y) {
    ull r; asm("mov.b64 %0, {%1, %2};" : "=l"(r) : "f"(x), "f"(y)); return r;
}
__device__ __forceinline__ void unpack2(ull v, float& x, float& y) {
    asm("mov.b64 {%0, %1}, %2;" : "=f"(x), "=f"(y) : "l"(v));
}
__device__ __forceinline__ void ffma2(ull& d, ull a, ull b) {
    asm("fma.rn.f32x2 %0, %1, %2, %3;" : "=l"(d) : "l"(a), "l"(b), "l"(d));
}
__device__ __forceinline__ void bar_sync_n(int id) {
    asm volatile("bar.sync %0, 256;" :: "r"(id) : "memory");
}
__device__ __forceinline__ void bar_arrive_n(int id) {
    asm volatile("bar.arrive %0, 256;" :: "r"(id) : "memory");
}

// -------- scratch --------
__device__ float g_luv[BATCH*4*PIX];
__device__ float g_hist_part[SPLITK][BATCH*E_HIST];
__device__ float g_c1L[BATCH*128*29*C1STR];
__device__ float g_c2p[4][BATCH*C2_PER];
__device__ float g_c2[BATCH*256*C2STR];
__device__ float g_c3p[4][BATCH*C3_PER];
__device__ float g_c3[BATCH*C3_PER];
__device__ float g_fc_part[FC_KC][BATCH*9];
__device__ float g_m[BATCH*9];
__device__ float g_minv[BATCH*9];
__device__ float g_w2t[W2T_N];
__device__ float g_w3t[W3T_N];

// ============================================================
// weight transposes: [oc][ic][k] -> [octile][ks][s][ic][k][ocl]
// ============================================================
__global__ void w2t_kernel(const float* __restrict__ w)
{
    int idx = blockIdx.x * 256 + threadIdx.x;
    if (idx >= W2T_N) return;
    int ocl = idx & 31;
    int t = idx >> 5;
    int k = t % 9; t /= 9;
    int ic = t & 7; t >>= 3;
    int s = t & 3; t >>= 2;
    int ks = t & 3; int octile = t >> 2;
    int oc = octile * 32 + ocl;
    int icg = ks * 32 + s * 8 + ic;
    g_w2t[idx] = w[((size_t)oc * 128 + icg) * 9 + k];
}
__global__ void w3t_kernel(const float* __restrict__ w)
{
    int idx = blockIdx.x * 256 + threadIdx.x;
    if (idx >= W3T_N) return;
    int ocl = idx & 31;
    int t = idx >> 5;
    int k = t & 3; t >>= 2;
    int ic = t & 15; t >>= 4;
    int s = t & 3; t >>= 2;
    int ks = t & 3; int octile = t >> 2;
    int oc = octile * 32 + ocl;
    int icg = ks * 64 + s * 16 + ic;
    g_w3t[idx] = w[((size_t)oc * 256 + icg) * 4 + k];
}

// ============================================================
// prep: image -> (lr,lg,lb,iy). mode 1: apply g_m first
// ============================================================
__global__ void prep_kernel(const float* __restrict__ img, int mapped)
{
    int idx = blockIdx.x * 256 + threadIdx.x;
    if (idx >= BATCH * PIX) return;
    int b = idx / PIX;
    int p = idx - b * PIX;
    float r  = img[(size_t)(b * 3 + 0) * PIX + p];
    float g  = img[(size_t)(b * 3 + 1) * PIX + p];
    float bl = img[(size_t)(b * 3 + 2) * PIX + p];
    if (mapped) {
        const float* M = &g_m[b * 9];
        float r2  = M[0]*r + M[1]*g + M[2]*bl;
        float g2  = M[3]*r + M[4]*g + M[5]*bl;
        float bl2 = M[6]*r + M[7]*g + M[8]*bl;
        r = r2; g = g2; bl = bl2;
    }
    r  = fminf(fmaxf(r, 0.f), 1.f);
    g  = fminf(fmaxf(g, 0.f), 1.f);
    bl = fminf(fmaxf(bl, 0.f), 1.f);
    float iy = sqrtf(r*r + g*g + bl*bl);
    g_luv[(size_t)(b*4 + 0)*PIX + p] = logf(r + 1e-6f);
    g_luv[(size_t)(b*4 + 1)*PIX + p] = logf(g + 1e-6f);
    g_luv[(size_t)(b*4 + 2)*PIX + p] = logf(bl + 1e-6f);
    g_luv[(size_t)(b*4 + 3)*PIX + p] = iy;
}

// ============================================================
// Histogram (R14 structure, unchanged — best measured variant)
// ============================================================
__global__ void __launch_bounds__(256, 3)
hist_kernel(const float* __restrict__ su,
            const float* __restrict__ sv,
            const float* __restrict__ cpar)
{
    extern __shared__ __align__(16) float smemDyn[];

    int blk = blockIdx.x;
    int ks  = blk % SPLITK;
    int bc  = blk / SPLITK;
    int c   = bc % 3;
    int b   = bc / 3;

    float sg_u = su[c], sg_v = sv[c];
    float inv_u2 = 1.0f / (sg_u * sg_u);
    float inv_v2 = 1.0f / (sg_v * sg_v);
    float cw = cpar[c];

    int tid = threadIdx.x;
    bool is_builder = (tid < 128);

    int k0 = ks * KCH;
    int k1 = min(k0 + KCH, PIX);
    int T  = (k1 - k0 + KT - 1) / KT;
    const float* luv = g_luv + (size_t)b * 4 * PIX;

    if (is_builder) {
        int pl  = tid & 63;
        int isV = (tid >> 6) & 1;
        float inv2 = isV ? inv_v2 : inv_u2;
        float q    = __expf(-0.02f * inv2);

        for (int t = 0; t < T; t++) {
            if (t >= 2) bar_sync_n(3 + (t & 1));
            float* base = smemDyn + (t & 1) * (2 * KT * KSTR);
            float* row  = base + isV * (KT * KSTR) + pl * KSTR;
            float4 z4 = make_float4(0.f, 0.f, 0.f, 0.f);
#pragma unroll
            for (int i = 0; i < 16; i++) ((float4*)row)[i] = z4;

            int p = k0 + t * KT + pl;
            bool valid = (p < k1);
            int pp = valid ? p : 0;
            float la  = luv[pp];
            float lgg = luv[PIX + pp];
            float lbb = luv[2*PIX + pp];
            float x, wgt;
            if (!isV) {
                float iy = luv[3*PIX + pp];
                if (c == 0)      x = la - lgg;
                else if (c == 1) x = lgg - la;
                else             x = lbb - la;
                wgt = valid ? iy * cw : 0.f;
            } else {
                if (c == 0)      x = la - lbb;
                else if (c == 1) x = lgg - lbb;
                else             x = lbb - lgg;
                wgt = 1.0f;
            }
            int cb = __float2int_rn((x + 3.0f) * 10.0f);
            cb = max(0, min(60, cb));
            float d = x - (-3.0f + 0.1f * (float)cb);
            float fc0 = __expf(-d * d * inv2) * wgt;
            float rup = __expf(( 0.2f * d - 0.01f) * inv2);
            float sdn = __expf((-0.2f * d - 0.01f) * inv2);
            row[cb] = fc0;
            float f = fc0, rr = rup;
#pragma unroll
            for (int j = 1; j <= 16; j++) {
                f *= rr; rr *= q;
                int b2 = cb + j;
                if (b2 <= 60) row[b2] = f;
            }
            f = fc0; rr = sdn;
#pragma unroll
            for (int j = 1; j <= 16; j++) {
                f *= rr; rr *= q;
                int b2 = cb - j;
                if (b2 >= 0) row[b2] = f;
            }
            bar_arrive_n(1 + (t & 1));
        }
    } else {
        int lx = tid - 128;
        int tx = lx & 15;
        int ty = lx >> 4;

        ull acc[8][2];
#pragma unroll
        for (int a = 0; a < 8; a++) { acc[a][0] = 0ULL; acc[a][1] = 0ULL; }

        for (int t = 0; t < T; t++) {
            bar_sync_n(1 + (t & 1));
            const float* base = smemDyn + (t & 1) * (2 * KT * KSTR);
            const float* bufU = base;
            const float* bufV = base + KT * KSTR;
#pragma unroll 2
            for (int k = 0; k < KT; k++) {
                const float4* Ur = (const float4*)(bufU + k * KSTR + ty * 8);
                float4 Ua = Ur[0], Ub = Ur[1];
                ulonglong2 V = *(const ulonglong2*)(bufV + k * KSTR + tx * 4);
                ull up[8];
                up[0] = pack2(Ua.x, Ua.x); up[1] = pack2(Ua.y, Ua.y);
                up[2] = pack2(Ua.z, Ua.z); up[3] = pack2(Ua.w, Ua.w);
                up[4] = pack2(Ub.x, Ub.x); up[5] = pack2(Ub.y, Ub.y);
                up[6] = pack2(Ub.z, Ub.z); up[7] = pack2(Ub.w, Ub.w);
#pragma unroll
                for (int a = 0; a < 8; a++) {
                    ffma2(acc[a][0], up[a], V.x);
                    ffma2(acc[a][1], up[a], V.y);
                }
            }
            bar_arrive_n(3 + (t & 1));
        }

        float* out = &g_hist_part[ks][(size_t)b * E_HIST + c * HB * HB];
#pragma unroll
        for (int a = 0; a < 8; a++) {
            int iu = ty * 8 + a;
            if (iu >= HB) continue;
#pragma unroll
            for (int j = 0; j < 2; j++) {
                float lo, hi;
                unpack2(acc[a][j], lo, hi);
                int iv = tx * 4 + 2 * j;
                if (iv < HB)     out[iu * HB + iv]     = lo;
                if (iv + 1 < HB) out[iu * HB + iv + 1] = hi;
            }
        }
    }
}

// ============================================================
// conv1: writes g_c1L in even/odd pre-split layout [b][oc][29][36]
// (even cols at 0..14, odd cols at 18..31).
// ============================================================
__global__ void conv1_kernel(const float* __restrict__ w, const float* __restrict__ bias)
{
    int octile = blockIdx.x;
    int b      = blockIdx.y;
    __shared__ __align__(16) float sInE[3][61][32];
    __shared__ __align__(16) float sInO[3][61][32];
    __shared__ __align__(16) float sW[1200];
    __shared__ float sRed[512];
    int tx = threadIdx.x;
    int ty = threadIdx.y;
    int tid = ty * 29 + tx;

    float lsum = 0.f;
    for (int i = tid; i < E_HIST; i += 435) {
        float h = 0.f;
#pragma unroll
        for (int s = 0; s < SPLITK; s++) h += g_hist_part[s][b * E_HIST + i];
        int ic = i / 3721; int pos = i - ic * 3721;
        int y = pos / 61;  int x = pos - y * 61;
        if (x & 1) sInO[ic][y][x >> 1] = h;
        else       sInE[ic][y][x >> 1] = h;
        lsum += h;
    }
    for (int i = tid; i < 1200; i += 435) {
        int ocl = i & 15; int rest = i >> 4;
        sW[i] = w[(size_t)(octile * 16 + ocl) * 75 + rest];
    }
    sRed[tid] = lsum;
    if (tid < 77) sRed[435 + tid] = 0.f;
    __syncthreads();
    for (int s = 256; s > 0; s >>= 1) {
        if (tid < s) sRed[tid] += sRed[tid + s];
        __syncthreads();
    }
    float inv = 1.0f / (sRed[0] + 1e-6f);

    ull acc[2][8];
#pragma unroll
    for (int p = 0; p < 2; p++)
#pragma unroll
        for (int t = 0; t < 8; t++) acc[p][t] = 0ULL;

    int r1 = min(ty + 15, 28);

#pragma unroll 1
    for (int ic = 0; ic < 3; ic++) {
#pragma unroll
        for (int ky = 0; ky < 5; ky++)
#pragma unroll
            for (int kx = 0; kx < 5; kx++) {
                int xi = tx + (kx >> 1);
                const float (*P)[32] = (kx & 1) ? sInO[ic] : sInE[ic];
                float v0 = P[2 * ty + ky][xi];
                float v1 = P[2 * r1 + ky][xi];
                ull p0 = pack2(v0, v0);
                ull p1 = pack2(v1, v1);
                const ulonglong2* wk = (const ulonglong2*)&sW[(ic * 25 + ky * 5 + kx) * 16];
                ulonglong2 wa = wk[0], wb = wk[1];
                ffma2(acc[0][0], p0, wa.x); ffma2(acc[0][1], p0, wa.y);
                ffma2(acc[0][2], p0, wb.x); ffma2(acc[0][3], p0, wb.y);
                ffma2(acc[1][0], p1, wa.x); ffma2(acc[1][1], p1, wa.y);
                ffma2(acc[1][2], p1, wb.x); ffma2(acc[1][3], p1, wb.y);
                ulonglong2 wc = wk[2], wd = wk[3];
                ffma2(acc[0][4], p0, wc.x); ffma2(acc[0][5], p0, wc.y);
                ffma2(acc[0][6], p0, wd.x); ffma2(acc[0][7], p0, wd.y);
                ffma2(acc[1][4], p1, wc.x); ffma2(acc[1][5], p1, wc.y);
                ffma2(acc[1][6], p1, wd.x); ffma2(acc[1][7], p1, wd.y);
            }
    }

    int pos = (tx & 1) ? 18 + (tx >> 1) : (tx >> 1);
#pragma unroll
    for (int p = 0; p < 2; p++) {
        int oy = ty + p * 15;
        if (oy > 28) continue;
#pragma unroll
        for (int t = 0; t < 8; t++) {
            float lo, hi;
            unpack2(acc[p][t], lo, hi);
            int oc = octile * 16 + 2 * t;
            g_c1L[((size_t)(b * 128 + oc) * 29 + oy) * C1STR + pos]     = fmaxf(bias[oc]     + inv * lo, 0.f);
            g_c1L[((size_t)(b * 128 + oc + 1) * 29 + oy) * C1STR + pos] = fmaxf(bias[oc + 1] + inv * hi, 0.f);
        }
    }
}

// ============================================================
// conv2: linear float4 smem fills (pre-split input, pre-transposed w)
// ============================================================
__global__ void conv2_kernel()
{
    int octile = blockIdx.x;
    int b      = blockIdx.y;
    int ks     = blockIdx.z;
    __shared__ __align__(16) float sIn[8 * 29 * C1STR];   // 33.4 KB
    __shared__ __align__(16) float sW[2304];              // 9 KB
    int tx = threadIdx.x;
    int ty = threadIdx.y;
    int z  = threadIdx.z;
    int tid = (z * 7 + ty) * 14 + tx;

    ull acc[2][8];
#pragma unroll
    for (int p = 0; p < 2; p++)
#pragma unroll
        for (int t = 0; t < 8; t++) acc[p][t] = 0ULL;

    for (int s = 0; s < 4; s++) {
        int icg = ks * 32 + s * 8;
        __syncthreads();
        const float4* src = (const float4*)&g_c1L[(size_t)(b * 128 + icg) * 29 * C1STR];
        for (int i = tid; i < 8 * 29 * C1STR / 4; i += 196)
            ((float4*)sIn)[i] = src[i];
        const float4* wsrc = (const float4*)&g_w2t[(((size_t)octile * 4 + ks) * 4 + s) * 2304];
        for (int i = tid; i < 576; i += 196)
            ((float4*)sW)[i] = wsrc[i];
        __syncthreads();
#pragma unroll
        for (int ic = 0; ic < 8; ic++) {
            const float* base = sIn + ic * 29 * C1STR;
            const float* wp = &sW[ic * 288 + z * 16];
#pragma unroll
            for (int ky = 0; ky < 3; ky++)
#pragma unroll
                for (int kx = 0; kx < 3; kx++) {
                    int cidx = (kx == 1) ? 18 + tx : tx + (kx >> 1);
                    float v0 = base[(2 * ty + ky) * C1STR + cidx];
                    float v1 = base[(2 * ty + ky + 14) * C1STR + cidx];
                    ull p0 = pack2(v0, v0);
                    ull p1 = pack2(v1, v1);
                    const ulonglong2* wk = (const ulonglong2*)(wp + (ky * 3 + kx) * 32);
                    ulonglong2 wa = wk[0], wb = wk[1];
                    ffma2(acc[0][0], p0, wa.x); ffma2(acc[0][1], p0, wa.y);
                    ffma2(acc[0][2], p0, wb.x); ffma2(acc[0][3], p0, wb.y);
                    ffma2(acc[1][0], p1, wa.x); ffma2(acc[1][1], p1, wa.y);
                    ffma2(acc[1][2], p1, wb.x); ffma2(acc[1][3], p1, wb.y);
                    ulonglong2 wc = wk[2], wd = wk[3];
                    ffma2(acc[0][4], p0, wc.x); ffma2(acc[0][5], p0, wc.y);
                    ffma2(acc[0][6], p0, wd.x); ffma2(acc[0][7], p0, wd.y);
                    ffma2(acc[1][4], p1, wc.x); ffma2(acc[1][5], p1, wc.y);
                    ffma2(acc[1][6], p1, wd.x); ffma2(acc[1][7], p1, wd.y);
                }
        }
    }
    float* outp = &g_c2p[ks][(size_t)b * C2_PER];
#pragma unroll
    for (int p = 0; p < 2; p++) {
        int oy = ty + p * 7;
#pragma unroll
        for (int t = 0; t < 8; t++) {
            float lo, hi;
            unpack2(acc[p][t], lo, hi);
            int oc = octile * 32 + z * 16 + 2 * t;
            outp[((size_t)oc * 14 + oy) * 14 + tx]       = lo;
            outp[((size_t)(oc + 1) * 14 + oy) * 14 + tx] = hi;
        }
    }
}

// division-free reduce; writes padded g_c2 [b][oc][212]
__global__ void conv2_reduce_kernel(const float* __restrict__ bias)
{
    int oc = blockIdx.x;   // 0..255
    int b  = blockIdx.y;   // 0..15
    int i  = threadIdx.x;  // 256
    if (i >= C2STR) return;
    float v = 0.f;
    if (i < 196) {
        v = bias[oc];
        size_t gidx = (size_t)b * C2_PER + oc * 196 + i;
#pragma unroll
        for (int k = 0; k < 4; k++) v += g_c2p[k][gidx];
        v = fmaxf(v, 0.f);
    }
    g_c2[(size_t)(b * 256 + oc) * C2STR + i] = v;
}

// ============================================================
// conv3: linear float4 smem fills (padded g_c2, pre-transposed w)
// ============================================================
__global__ void conv3_kernel()
{
    int octile = blockIdx.x;
    int b      = blockIdx.y;
    int ks     = blockIdx.z;
    __shared__ __align__(16) float sIn[16 * C2STR];   // 13.6 KB
    __shared__ __align__(16) float sW[2048];          // 8 KB
    int tx = threadIdx.x;
    int ty = threadIdx.y;
    int z  = threadIdx.z;
    int tid = (z * 7 + ty) * 13 + tx;

    ull acc[2][8];
#pragma unroll
    for (int p = 0; p < 2; p++)
#pragma unroll
        for (int t = 0; t < 8; t++) acc[p][t] = 0ULL;

    for (int s = 0; s < 4; s++) {
        int icg = ks * 64 + s * 16;
        __syncthreads();
        const float4* src = (const float4*)&g_c2[(size_t)(b * 256 + icg) * C2STR];
        for (int i = tid; i < 16 * C2STR / 4; i += 182)
            ((float4*)sIn)[i] = src[i];
        const float4* wsrc = (const float4*)&g_w3t[(((size_t)octile * 4 + ks) * 4 + s) * 2048];
        for (int i = tid; i < 512; i += 182)
            ((float4*)sW)[i] = wsrc[i];
        __syncthreads();
#pragma unroll
        for (int ic = 0; ic < 16; ic++) {
            const float* ip = &sIn[ic * C2STR + ty * 14 + tx];
            const float* wp = &sW[ic * 128 + z * 16];
#pragma unroll
            for (int ky = 0; ky < 2; ky++)
#pragma unroll
                for (int kx = 0; kx < 2; kx++) {
                    float v0 = ip[ky * 14 + kx];
                    float v1 = ip[ky * 14 + kx + 98];
                    ull p0 = pack2(v0, v0);
                    ull p1 = pack2(v1, v1);
                    const ulonglong2* wk = (const ulonglong2*)(wp + (ky * 2 + kx) * 32);
                    ulonglong2 wa = wk[0], wb = wk[1];
                    ffma2(acc[0][0], p0, wa.x); ffma2(acc[0][1], p0, wa.y);
                    ffma2(acc[0][2], p0, wb.x); ffma2(acc[0][3], p0, wb.y);
                    ffma2(acc[1][0], p1, wa.x); ffma2(acc[1][1], p1, wa.y);
                    ffma2(acc[1][2], p1, wb.x); ffma2(acc[1][3], p1, wb.y);
                    ulonglong2 wc = wk[2], wd = wk[3];
                    ffma2(acc[0][4], p0, wc.x); ffma2(acc[0][5], p0, wc.y);
                    ffma2(acc[0][6], p0, wd.x); ffma2(acc[0][7], p0, wd.y);
                    ffma2(acc[1][4], p1, wc.x); ffma2(acc[1][5], p1, wc.y);
                    ffma2(acc[1][6], p1, wd.x); ffma2(acc[1][7], p1, wd.y);
                }
        }
    }
    float* outp = &g_c3p[ks][(size_t)b * C3_PER];
#pragma unroll
    for (int p = 0; p < 2; p++) {
        int oy = ty + p * 7;
        if (oy > 12) continue;
#pragma unroll
        for (int t = 0; t < 8; t++) {
            float lo, hi;
            unpack2(acc[p][t], lo, hi);
            int oc = octile * 32 + z * 16 + 2 * t;
            outp[((size_t)oc * 13 + oy) * 13 + tx]       = lo;
            outp[((size_t)(oc + 1) * 13 + oy) * 13 + tx] = hi;
        }
    }
}

__global__ void conv3_reduce_kernel(const float* __restrict__ bias)
{
    int idx = blockIdx.x * 256 + threadIdx.x;
    if (idx >= BATCH * C3_PER) return;
    int within = idx % C3_PER;
    int oc = within / 169;
    float s = bias[oc];
#pragma unroll
    for (int k = 0; k < 4; k++) s += g_c3p[k][idx];
    g_c3[idx] = fmaxf(s, 0.f);
}

// ============================================================
// fc (split-K) — R15 structure
// ============================================================
template<int OUT>
__global__ void fc_kernel(const float* __restrict__ w)
{
    int kc = blockIdx.x;
    int bg = blockIdx.y;
    int tid = threadIdx.x;
    int lane = tid & 31, wid = tid >> 5;
    int base4 = kc * FC_CH4;

    float acc[4][OUT];
#pragma unroll
    for (int bi = 0; bi < 4; bi++)
#pragma unroll
        for (int o = 0; o < OUT; o++) acc[bi][o] = 0.f;

    const float4* act = (const float4*)g_c3;
    const float4* wv4 = (const float4*)w;

    for (int i = tid; i < FC_CH4; i += 256) {
        float4 a[4];
#pragma unroll
        for (int bi = 0; bi < 4; bi++)
            a[bi] = act[(size_t)(bg * 4 + bi) * (C3_PER / 4) + base4 + i];
#pragma unroll
        for (int o = 0; o < OUT; o++) {
            float4 wv = wv4[(size_t)o * (C3_PER / 4) + base4 + i];
#pragma unroll
            for (int bi = 0; bi < 4; bi++)
                acc[bi][o] += a[bi].x * wv.x + a[bi].y * wv.y
                            + a[bi].z * wv.z + a[bi].w * wv.w;
        }
    }

    __shared__ float red[8][4 * OUT];
#pragma unroll
    for (int bi = 0; bi < 4; bi++)
#pragma unroll
        for (int o = 0; o < OUT; o++) {
            float v = acc[bi][o];
#pragma unroll
            for (int s = 16; s > 0; s >>= 1)
                v += __shfl_down_sync(0xffffffffu, v, s);
            if (lane == 0) red[wid][bi * OUT + o] = v;
        }
    __syncthreads();
    if (tid < 4 * OUT) {
        float s = 0.f;
#pragma unroll
        for (int wg = 0; wg < 8; wg++) s += red[wg][tid];
        int bi = tid / OUT, o = tid % OUT;
        g_fc_part[kc][(bg * 4 + bi) * OUT + o] = s;
    }
}

// ============================================================
__global__ void matrix_kernel()
{
    int b = threadIdx.x;
    if (b >= BATCH) return;
    float v[9];
#pragma unroll
    for (int o = 0; o < 9; o++) {
        float s = 0.f;
#pragma unroll
        for (int kc = 0; kc < FC_KC; kc++) s += g_fc_part[kc][b * 9 + o];
        v[o] = fabsf(s);
    }
    float m[3][3];
#pragma unroll
    for (int i = 0; i < 3; i++)
#pragma unroll
        for (int j = 0; j < 3; j++) m[i][j] = v[j * 3 + i];
    float n = 0.f;
#pragma unroll
    for (int i = 0; i < 3; i++) {
        float rs = fabsf(m[i][0]) + fabsf(m[i][1]) + fabsf(m[i][2]);
        n = fmaxf(n, rs);
    }
    n += 1e-4f;
    float inv_n = 1.0f / n;
#pragma unroll
    for (int i = 0; i < 3; i++)
#pragma unroll
        for (int j = 0; j < 3; j++) {
            m[i][j] *= inv_n;
            g_m[b * 9 + i * 3 + j] = m[i][j];
        }
    float c00 = m[1][1]*m[2][2] - m[1][2]*m[2][1];
    float c01 = m[1][0]*m[2][2] - m[1][2]*m[2][0];
    float c02 = m[1][0]*m[2][1] - m[1][1]*m[2][0];
    float det = m[0][0]*c00 - m[0][1]*c01 + m[0][2]*c02;
    float id = 1.0f / det;
    g_minv[b*9 + 0] =  c00 * id;
    g_minv[b*9 + 1] = (m[0][2]*m[2][1] - m[0][1]*m[2][2]) * id;
    g_minv[b*9 + 2] = (m[0][1]*m[1][2] - m[0][2]*m[1][1]) * id;
    g_minv[b*9 + 3] = -c01 * id;
    g_minv[b*9 + 4] = (m[0][0]*m[2][2] - m[0][2]*m[2][0]) * id;
    g_minv[b*9 + 5] = (m[0][2]*m[1][0] - m[0][0]*m[1][2]) * id;
    g_minv[b*9 + 6] =  c02 * id;
    g_minv[b*9 + 7] = (m[0][1]*m[2][0] - m[0][0]*m[2][1]) * id;
    g_minv[b*9 + 8] = (m[0][0]*m[1][1] - m[0][1]*m[1][0]) * id;
}

__global__ void final_kernel(float* __restrict__ out)
{
    int b = threadIdx.x;
    if (b >= BATCH) return;
    float il[3];
#pragma unroll
    for (int j = 0; j < 3; j++) {
        float s = 0.f;
#pragma unroll
        for (int kc = 0; kc < FC_KC; kc++) s += g_fc_part[kc][b * 3 + j];
        il[j] = fabsf(s);
    }
#pragma unroll
    for (int i = 0; i < 3; i++)
        out[b * 3 + i] = g_minv[b*9 + i*3 + 0] * il[0]
                       + g_minv[b*9 + i*3 + 1] * il[1]
                       + g_minv[b*9 + i*3 + 2] * il[2];
}

// ============================================================
extern "C" void kernel_launch(void* const* d_in, const int* in_sizes, int n_in,
                              void* d_out, int out_size)
{
    const float* image = (const float*)d_in[0];
    const float* su_s  = (const float*)d_in[1];
    const float* sv_s  = (const float*)d_in[2];
    const float* c_s   = (const float*)d_in[3];
    const float* w1_s  = (const float*)d_in[4];
    const float* b1_s  = (const float*)d_in[5];
    const float* w2_s  = (const float*)d_in[6];
    const float* b2_s  = (const float*)d_in[7];
    const float* w3_s  = (const float*)d_in[8];
    const float* b3_s  = (const float*)d_in[9];
    const float* fc_s  = (const float*)d_in[10];
    const float* su_i  = (const float*)d_in[11];
    const float* sv_i  = (const float*)d_in[12];
    const float* c_i   = (const float*)d_in[13];
    const float* w1_i  = (const float*)d_in[14];
    const float* b1_i  = (const float*)d_in[15];
    const float* w2_i  = (const float*)d_in[16];
    const float* b2_i  = (const float*)d_in[17];
    const float* w3_i  = (const float*)d_in[18];
    const float* b3_i  = (const float*)d_in[19];
    const float* fc_i  = (const float*)d_in[20];

    static int smem_set = 0;
    if (!smem_set) {
        cudaFuncSetAttribute(hist_kernel,
                             cudaFuncAttributeMaxDynamicSharedMemorySize, HIST_SMEM);
        smem_set = 1;
    }

    dim3 cb1(29, 15), cb2(14, 7, 2), cb3(13, 7, 2);
    dim3 cg1(8, BATCH), cg2(8, BATCH, 4), cg3(16, BATCH, 4);
    dim3 cgr2(256, BATCH);
    dim3 cgfc(FC_KC, 4);
    int prep_blocks = (BATCH * PIX + 255) / 256;
    int c3r_blocks = (BATCH * C3_PER + 255) / 256;
    int w2t_blocks = (W2T_N + 255) / 256;
    int w3t_blocks = (W3T_N + 255) / 256;

    // ---- sensor branch ----
    w2t_kernel<<<w2t_blocks, 256>>>(w2_s);
    w3t_kernel<<<w3t_blocks, 256>>>(w3_s);
    prep_kernel<<<prep_blocks, 256>>>(image, 0);
    hist_kernel<<<BATCH * 3 * SPLITK, 256, HIST_SMEM>>>(su_s, sv_s, c_s);  // 4th -> ncu
    conv1_kernel<<<cg1, cb1>>>(w1_s, b1_s);
    conv2_kernel<<<cg2, cb2>>>();
    conv2_reduce_kernel<<<cgr2, 256>>>(b2_s);
    conv3_kernel<<<cg3, cb3>>>();
    conv3_reduce_kernel<<<c3r_blocks, 256>>>(b3_s);
    fc_kernel<9><<<cgfc, 256>>>(fc_s);
    matrix_kernel<<<1, 32>>>();

    // ---- illuminant branch ----
    w2t_kernel<<<w2t_blocks, 256>>>(w2_i);
    w3t_kernel<<<w3t_blocks, 256>>>(w3_i);
    prep_kernel<<<prep_blocks, 256>>>(image, 1);
    hist_kernel<<<BATCH * 3 * SPLITK, 256, HIST_SMEM>>>(su_i, sv_i, c_i);
    conv1_kernel<<<cg1, cb1>>>(w1_i, b1_i);
    conv2_kernel<<<cg2, cb2>>>();
    conv2_reduce_kernel<<<cgr2, 256>>>(b2_i);
    conv3_kernel<<<cg3, cb3>>>();
    conv3_reduce_kernel<<<c3r_blocks, 256>>>(b3_i);
    fc_kernel<3><<<cgfc, 256>>>(fc_i);
    final_kernel<<<1, 32>>>((float*)d_out);
}